// round 10
// baseline (speedup 1.0000x reference)
#include <cuda_runtime.h>
#include <cuda_bf16.h>
#include <cstdint>

#define B_   4
#define S_   2048
#define H_   16
#define D_   64
#define HID  1024
#define M_   (B_ * S_)

#define LOG2E 1.4426950408889634f

__device__ float g_Q[B_ * H_ * S_ * D_];
__device__ float g_K[B_ * H_ * S_ * D_];
__device__ float g_V[B_ * H_ * S_ * D_];

__device__ __forceinline__ uint32_t pack_f16x2(float lo, float hi) {
    uint32_t r;
    asm("cvt.rn.f16x2.f32 %0, %1, %2;" : "=r"(r) : "f"(hi), "f"(lo));
    return r;
}
__device__ __forceinline__ float ex2(float x) {
    float r;
    asm("ex2.approx.f32 %0, %1;" : "=f"(r) : "f"(x));
    return r;
}
__device__ __forceinline__ uint32_t smem_u32(const void* p) {
    uint32_t a;
    asm("{ .reg .u64 t; cvta.to.shared.u64 t, %1; cvt.u32.u64 %0, t; }" : "=r"(a) : "l"(p));
    return a;
}
__device__ __forceinline__ void cp16(uint32_t saddr, const void* gptr) {
    asm volatile("cp.async.ca.shared.global [%0], [%1], 16;" :: "r"(saddr), "l"(gptr));
}
#define CP_COMMIT() asm volatile("cp.async.commit_group;" ::: "memory")
#define CP_WAIT0()  asm volatile("cp.async.wait_group 0;" ::: "memory")

#define MMA_F16(c, a, b)                                               \
    asm volatile(                                                      \
        "mma.sync.aligned.m16n8k16.row.col.f32.f16.f16.f32 "           \
        "{%0,%1,%2,%3}, {%4,%5,%6,%7}, {%8,%9}, {%0,%1,%2,%3};\n"      \
        : "+f"((c)[0]), "+f"((c)[1]), "+f"((c)[2]), "+f"((c)[3])       \
        : "r"((a)[0]), "r"((a)[1]), "r"((a)[2]), "r"((a)[3]),          \
          "r"((b)[0]), "r"((b)[1]))

// ---------------------------------------------------------------------------
// Kernel A: fused QKV GEMM in fp16 (unchanged from R8/R9).
// ---------------------------------------------------------------------------
#define AH_S 20
#define BP_S 136
#define AH_W (128 * AH_S)
#define BP_W (16 * BP_S)
#define STG_W (AH_W + BP_W)
#define GEMM_SMEM (2 * STG_W * 4)

__global__ __launch_bounds__(256) void qkv_gemm3(const float* __restrict__ X,
                                                 const float* __restrict__ Wq,
                                                 const float* __restrict__ Wk,
                                                 const float* __restrict__ Wv,
                                                 const float* __restrict__ bq,
                                                 const float* __restrict__ bk,
                                                 const float* __restrict__ bv,
                                                 float* __restrict__ oQ,
                                                 float* __restrict__ oK,
                                                 float* __restrict__ oV)
{
    extern __shared__ uint32_t smg[];

    const int z = blockIdx.z;
    const float* W    = (z == 0) ? Wq : (z == 1) ? Wk : Wv;
    const float* bias = (z == 0) ? bq : (z == 1) ? bk : bv;
    float* outh       = (z == 0) ? oQ : (z == 1) ? oK : oV;

    const int tid  = threadIdx.x;
    const int warp = tid >> 5;
    const int lane = tid & 31;
    const int grp  = lane >> 2;
    const int thr  = lane & 3;
    const int wm   = warp >> 2;
    const int wn   = warp & 3;
    const int m0   = blockIdx.y * 128;
    const int n0   = blockIdx.x * 128;

    float acc[4][4][4];
    #pragma unroll
    for (int mt = 0; mt < 4; ++mt)
        #pragma unroll
        for (int nt = 0; nt < 4; ++nt)
            #pragma unroll
            for (int r = 0; r < 4; ++r) acc[mt][nt][r] = 0.f;

    float4 avr[4], b0r[2], b1r[2];
    #pragma unroll
    for (int t = 0; t < 4; ++t) {
        int i = tid + t * 256;
        int row = i >> 3, q = i & 7;
        avr[t] = *reinterpret_cast<const float4*>(&X[(size_t)(m0 + row) * HID + q * 4]);
    }
    #pragma unroll
    for (int t = 0; t < 2; ++t) {
        int i = tid + t * 256;
        int kp = i >> 5, n4 = (i & 31) * 4;
        b0r[t] = *reinterpret_cast<const float4*>(&W[(size_t)(2 * kp)     * HID + n0 + n4]);
        b1r[t] = *reinterpret_cast<const float4*>(&W[(size_t)(2 * kp + 1) * HID + n0 + n4]);
    }
    #pragma unroll
    for (int t = 0; t < 4; ++t) {
        int i = tid + t * 256;
        int row = i >> 3, q = i & 7;
        uint2 u = {pack_f16x2(avr[t].x, avr[t].y), pack_f16x2(avr[t].z, avr[t].w)};
        *reinterpret_cast<uint2*>(&smg[row * AH_S + 2 * q]) = u;
    }
    #pragma unroll
    for (int t = 0; t < 2; ++t) {
        int i = tid + t * 256;
        int kp = i >> 5, n4 = (i & 31) * 4;
        uint4 u = {pack_f16x2(b0r[t].x, b1r[t].x), pack_f16x2(b0r[t].y, b1r[t].y),
                   pack_f16x2(b0r[t].z, b1r[t].z), pack_f16x2(b0r[t].w, b1r[t].w)};
        *reinterpret_cast<uint4*>(&smg[AH_W + kp * BP_S + n4]) = u;
    }
    __syncthreads();

    for (int i = 0; i < 32; ++i) {
        const uint32_t* Ah = smg + (i & 1) * STG_W;
        const uint32_t* Bp = Ah + AH_W;
        if (i + 1 < 32) {
            const int kn = (i + 1) * 32;
            #pragma unroll
            for (int t = 0; t < 4; ++t) {
                int ii = tid + t * 256;
                int row = ii >> 3, q = ii & 7;
                avr[t] = *reinterpret_cast<const float4*>(&X[(size_t)(m0 + row) * HID + kn + q * 4]);
            }
            #pragma unroll
            for (int t = 0; t < 2; ++t) {
                int ii = tid + t * 256;
                int kp = ii >> 5, n4 = (ii & 31) * 4;
                b0r[t] = *reinterpret_cast<const float4*>(&W[(size_t)(kn + 2 * kp)     * HID + n0 + n4]);
                b1r[t] = *reinterpret_cast<const float4*>(&W[(size_t)(kn + 2 * kp + 1) * HID + n0 + n4]);
            }
        }
        #pragma unroll
        for (int s = 0; s < 2; ++s) {
            uint32_t a[4][4], b[4][2];
            #pragma unroll
            for (int mt = 0; mt < 4; ++mt) {
                int r = wm * 64 + mt * 16 + grp;
                a[mt][0] = Ah[r * AH_S + s * 8 + thr];
                a[mt][1] = Ah[(r + 8) * AH_S + s * 8 + thr];
                a[mt][2] = Ah[r * AH_S + s * 8 + 4 + thr];
                a[mt][3] = Ah[(r + 8) * AH_S + s * 8 + 4 + thr];
            }
            #pragma unroll
            for (int nt = 0; nt < 4; ++nt) {
                int c = wn * 32 + nt * 8 + grp;
                b[nt][0] = Bp[(s * 8 + thr)     * BP_S + c];
                b[nt][1] = Bp[(s * 8 + thr + 4) * BP_S + c];
            }
            #pragma unroll
            for (int mt = 0; mt < 4; ++mt)
                #pragma unroll
                for (int nt = 0; nt < 4; ++nt)
                    MMA_F16(acc[mt][nt], a[mt], b[nt]);
        }
        if (i + 1 < 32) {
            uint32_t* Ad = smg + ((i + 1) & 1) * STG_W;
            uint32_t* Bd = Ad + AH_W;
            #pragma unroll
            for (int t = 0; t < 4; ++t) {
                int ii = tid + t * 256;
                int row = ii >> 3, q = ii & 7;
                uint2 u = {pack_f16x2(avr[t].x, avr[t].y), pack_f16x2(avr[t].z, avr[t].w)};
                *reinterpret_cast<uint2*>(&Ad[row * AH_S + 2 * q]) = u;
            }
            #pragma unroll
            for (int t = 0; t < 2; ++t) {
                int ii = tid + t * 256;
                int kp = ii >> 5, n4 = (ii & 31) * 4;
                uint4 u = {pack_f16x2(b0r[t].x, b1r[t].x), pack_f16x2(b0r[t].y, b1r[t].y),
                           pack_f16x2(b0r[t].z, b1r[t].z), pack_f16x2(b0r[t].w, b1r[t].w)};
                *reinterpret_cast<uint4*>(&Bd[kp * BP_S + n4]) = u;
            }
        }
        __syncthreads();
    }

    #pragma unroll
    for (int mt = 0; mt < 4; ++mt) {
        #pragma unroll
        for (int nt = 0; nt < 4; ++nt) {
            #pragma unroll
            for (int half = 0; half < 2; ++half) {
                int m = m0 + wm * 64 + mt * 16 + grp + half * 8;
                int bb = m >> 11, s = m & 2047;
                int n = n0 + wn * 32 + nt * 8 + 2 * thr;
                int h = n >> 6, d = n & 63;
                float2 v = {acc[mt][nt][half * 2 + 0] + bias[n],
                            acc[mt][nt][half * 2 + 1] + bias[n + 1]};
                *reinterpret_cast<float2*>(
                    &outh[(((size_t)(bb * H_ + h) * S_) + s) * D_ + d]) = v;
            }
        }
    }
}

// ---------------------------------------------------------------------------
// Kernel B: persistent flash attention, all-fp16 mma, exp2 softmax.
// Grid = 296 persistent blocks looping over 2048 (b,h,q0) items.
// ---------------------------------------------------------------------------
#define QH 36
#define KR 68
#define KP 36
#define VP 72
#define QW2     (128 * QH)
#define OFF_KR0 QW2
#define OFF_KR1 (QW2 + 64 * KR)
#define OFF_KP  (OFF_KR1 + 64 * KR)
#define OFF_V   (OFF_KP + 64 * KP)
#define OFF_M0  (OFF_V + 32 * VP)
#define OFF_M1  (OFF_M0 + 64)
#define ATTN_WORDS (OFF_M1 + 64)
#define NWORK   (B_ * H_ * (S_ / 128))    // 2048
#define PGRID   296

__global__ __launch_bounds__(128) void attn_f16(const float* __restrict__ Q,
                                                const float* __restrict__ K,
                                                const float* __restrict__ V,
                                                const float* __restrict__ mask,
                                                float* __restrict__ out)
{
    extern __shared__ uint32_t sm[];
    const uint32_t sbase = smem_u32(sm);

    const int tid  = threadIdx.x;
    const int warp = tid >> 5;
    const int lane = tid & 31;
    const int grp  = lane >> 2;
    const int thr  = lane & 3;
    const int wr0  = warp * 32;
    const int kr   = tid >> 4;
    const int kc4  = (tid & 15) * 4;

    for (int w = blockIdx.x; w < NWORK; w += PGRID) {
        const int q0 = (w & 15) * 128;
        const int h  = (w >> 4) & 15;
        const int b  = w >> 8;
        const size_t base = (size_t)(b * H_ + h) * S_ * D_;

        // ---- prologue: Q -> fp16 (prescaled by log2e/8), K tile0 + mask ----
        #pragma unroll
        for (int t = 0; t < 16; ++t) {
            int i = tid + t * 128;
            int r = i >> 4, c = (i & 15) * 4;
            float4 v = *reinterpret_cast<const float4*>(&Q[base + (size_t)(q0 + r) * D_ + c]);
            const float sc = 0.125f * LOG2E;
            uint2 u = {pack_f16x2(v.x * sc, v.y * sc), pack_f16x2(v.z * sc, v.w * sc)};
            *reinterpret_cast<uint2*>(&sm[r * QH + (c >> 1)]) = u;
        }
        #pragma unroll
        for (int t = 0; t < 8; ++t) {
            int r = kr + t * 8;
            cp16(sbase + (OFF_KR0 + r * KR + kc4) * 4, &K[base + (size_t)r * D_ + kc4]);
        }
        if (tid < 16) cp16(sbase + (OFF_M0 + tid * 4) * 4, &mask[b * S_ + tid * 4]);
        CP_COMMIT();

        float4 vr[8];
        #pragma unroll
        for (int t = 0; t < 4; ++t) {
            int i = tid + t * 128;
            int r2 = i >> 4, c = (i & 15) * 4;
            vr[2 * t]     = *reinterpret_cast<const float4*>(&V[base + (size_t)(2 * r2)     * D_ + c]);
            vr[2 * t + 1] = *reinterpret_cast<const float4*>(&V[base + (size_t)(2 * r2 + 1) * D_ + c]);
        }

        float mrun[4] = {-1e30f, -1e30f, -1e30f, -1e30f};
        float lrun[4] = {0.f, 0.f, 0.f, 0.f};
        float o[2][8][4];
        #pragma unroll
        for (int at = 0; at < 2; ++at)
            #pragma unroll
            for (int nt = 0; nt < 8; ++nt)
                #pragma unroll
                for (int r = 0; r < 4; ++r) o[at][nt][r] = 0.f;

        for (int it = 0; it < 32; ++it) {
            const int bu = it & 1;
            const float* Kraw = (const float*)(sm + (bu ? OFF_KR1 : OFF_KR0));
            float* mskw = (float*)(sm + (bu ? OFF_M1 : OFF_M0));

            CP_WAIT0();
            __syncthreads();

            // stage V(it) (single buffer), convert K raw->fp16, scale mask by log2e
            #pragma unroll
            for (int t = 0; t < 4; ++t) {
                int i = tid + t * 128;
                int r2 = i >> 4, c = (i & 15) * 4;
                float4 v0 = vr[2 * t], v1 = vr[2 * t + 1];
                uint4 u = {pack_f16x2(v0.x, v1.x), pack_f16x2(v0.y, v1.y),
                           pack_f16x2(v0.z, v1.z), pack_f16x2(v0.w, v1.w)};
                *reinterpret_cast<uint4*>(&sm[OFF_V + r2 * VP + c]) = u;
            }
            #pragma unroll
            for (int t = 0; t < 8; ++t) {
                int i = tid + t * 128;
                int key = i >> 4, c = (i & 15) * 4;
                float4 kv = *reinterpret_cast<const float4*>(&Kraw[key * KR + c]);
                uint2 u = {pack_f16x2(kv.x, kv.y), pack_f16x2(kv.z, kv.w)};
                *reinterpret_cast<uint2*>(&sm[OFF_KP + key * KP + (c >> 1)]) = u;
            }
            if (tid < 64) mskw[tid] *= LOG2E;

            if (it + 1 < 32) {
                const int kn = (it + 1) * 64;
                const uint32_t koff = bu ? OFF_KR0 : OFF_KR1;
                #pragma unroll
                for (int t = 0; t < 8; ++t) {
                    int r = kr + t * 8;
                    cp16(sbase + (koff + r * KR + kc4) * 4,
                         &K[base + (size_t)(kn + r) * D_ + kc4]);
                }
                if (tid < 16)
                    cp16(sbase + ((bu ? OFF_M0 : OFF_M1) + tid * 4) * 4,
                         &mask[b * S_ + kn + tid * 4]);
                CP_COMMIT();
                #pragma unroll
                for (int t = 0; t < 4; ++t) {
                    int i = tid + t * 128;
                    int r2 = i >> 4, c = (i & 15) * 4;
                    vr[2 * t]     = *reinterpret_cast<const float4*>(&V[base + (size_t)(kn + 2 * r2)     * D_ + c]);
                    vr[2 * t + 1] = *reinterpret_cast<const float4*>(&V[base + (size_t)(kn + 2 * r2 + 1) * D_ + c]);
                }
            }
            __syncthreads();

            // ---- S = Q @ K^T (fp16 k16; scores in log2 domain) ----
            float s[2][8][4];
            #pragma unroll
            for (int at = 0; at < 2; ++at)
                #pragma unroll
                for (int nt = 0; nt < 8; ++nt)
                    #pragma unroll
                    for (int r = 0; r < 4; ++r) s[at][nt][r] = 0.f;

            #pragma unroll
            for (int ks = 0; ks < 4; ++ks) {
                uint32_t bfr[8][2];
                #pragma unroll
                for (int nt = 0; nt < 8; ++nt) {
                    int key = nt * 8 + grp;
                    bfr[nt][0] = sm[OFF_KP + key * KP + ks * 8 + thr];
                    bfr[nt][1] = sm[OFF_KP + key * KP + ks * 8 + 4 + thr];
                }
                #pragma unroll
                for (int at = 0; at < 2; ++at) {
                    int r0 = wr0 + at * 16 + grp;
                    uint32_t a[4];
                    a[0] = sm[r0 * QH + ks * 8 + thr];
                    a[1] = sm[(r0 + 8) * QH + ks * 8 + thr];
                    a[2] = sm[r0 * QH + ks * 8 + 4 + thr];
                    a[3] = sm[(r0 + 8) * QH + ks * 8 + 4 + thr];
                    #pragma unroll
                    for (int nt = 0; nt < 8; ++nt)
                        MMA_F16(s[at][nt], a, bfr[nt]);
                }
            }

            // ---- mask + online softmax (base-2); P -> f16x2 in registers ----
            const float* msk = mskw;
            uint32_t pb[2][8][2];
            #pragma unroll
            for (int at = 0; at < 2; ++at) {
                float rmax0 = -1e30f, rmax1 = -1e30f;
                #pragma unroll
                for (int nt = 0; nt < 8; ++nt) {
                    int c0 = nt * 8 + 2 * thr;
                    float mk0 = msk[c0], mk1 = msk[c0 + 1];
                    s[at][nt][0] += mk0;  s[at][nt][1] += mk1;
                    s[at][nt][2] += mk0;  s[at][nt][3] += mk1;
                    rmax0 = fmaxf(rmax0, fmaxf(s[at][nt][0], s[at][nt][1]));
                    rmax1 = fmaxf(rmax1, fmaxf(s[at][nt][2], s[at][nt][3]));
                }
                rmax0 = fmaxf(rmax0, __shfl_xor_sync(0xffffffffu, rmax0, 1));
                rmax0 = fmaxf(rmax0, __shfl_xor_sync(0xffffffffu, rmax0, 2));
                rmax1 = fmaxf(rmax1, __shfl_xor_sync(0xffffffffu, rmax1, 1));
                rmax1 = fmaxf(rmax1, __shfl_xor_sync(0xffffffffu, rmax1, 2));

                const int g0 = at * 2, g1 = at * 2 + 1;
                const float mnew0 = fmaxf(mrun[g0], rmax0);
                const float mnew1 = fmaxf(mrun[g1], rmax1);
                float sum0 = 0.f, sum1 = 0.f;
                #pragma unroll
                for (int nt = 0; nt < 8; ++nt) {
                    s[at][nt][0] = ex2(s[at][nt][0] - mnew0);
                    s[at][nt][1] = ex2(s[at][nt][1] - mnew0);
                    s[at][nt][2] = ex2(s[at][nt][2] - mnew1);
                    s[at][nt][3] = ex2(s[at][nt][3] - mnew1);
                    sum0 += s[at][nt][0] + s[at][nt][1];
                    sum1 += s[at][nt][2] + s[at][nt][3];
                    pb[at][nt][0] = pack_f16x2(s[at][nt][0], s[at][nt][1]);
                    pb[at][nt][1] = pack_f16x2(s[at][nt][2], s[at][nt][3]);
                }
                sum0 += __shfl_xor_sync(0xffffffffu, sum0, 1);
                sum0 += __shfl_xor_sync(0xffffffffu, sum0, 2);
                sum1 += __shfl_xor_sync(0xffffffffu, sum1, 1);
                sum1 += __shfl_xor_sync(0xffffffffu, sum1, 2);

                const float cf0 = ex2(mrun[g0] - mnew0);
                const float cf1 = ex2(mrun[g1] - mnew1);
                mrun[g0] = mnew0;  lrun[g0] = lrun[g0] * cf0 + sum0;
                mrun[g1] = mnew1;  lrun[g1] = lrun[g1] * cf1 + sum1;

                #pragma unroll
                for (int nt = 0; nt < 8; ++nt) {
                    o[at][nt][0] *= cf0;  o[at][nt][1] *= cf0;
                    o[at][nt][2] *= cf1;  o[at][nt][3] *= cf1;
                }
            }

            // ---- O += P @ V (fp16 k16, A from registers) ----
            #pragma unroll
            for (int sstep = 0; sstep < 4; ++sstep) {
                uint32_t bfr[8][2];
                #pragma unroll
                for (int nt = 0; nt < 8; ++nt) {
                    int d = nt * 8 + grp;
                    bfr[nt][0] = sm[OFF_V + (sstep * 8 + thr)     * VP + d];
                    bfr[nt][1] = sm[OFF_V + (sstep * 8 + thr + 4) * VP + d];
                }
                #pragma unroll
                for (int at = 0; at < 2; ++at) {
                    uint32_t a[4] = {pb[at][2 * sstep][0], pb[at][2 * sstep][1],
                                     pb[at][2 * sstep + 1][0], pb[at][2 * sstep + 1][1]};
                    #pragma unroll
                    for (int nt = 0; nt < 8; ++nt)
                        MMA_F16(o[at][nt], a, bfr[nt]);
                }
            }
        }

        // Output: [B, S, H*Dh]
        #pragma unroll
        for (int at = 0; at < 2; ++at) {
            #pragma unroll
            for (int half = 0; half < 2; ++half) {
                const int g = at * 2 + half;
                const float inv = 1.f / lrun[g];
                const int q = q0 + wr0 + at * 16 + grp + half * 8;
                #pragma unroll
                for (int nt = 0; nt < 8; ++nt) {
                    int d = nt * 8 + 2 * thr;
                    float2 v = {o[at][nt][half * 2 + 0] * inv,
                                o[at][nt][half * 2 + 1] * inv};
                    *reinterpret_cast<float2*>(
                        &out[((size_t)(b * S_ + q)) * HID + h * D_ + d]) = v;
                }
            }
        }
        __syncthreads();   // output reads of l/o done before next item's staging
    }
}

// ---------------------------------------------------------------------------
// Launch
// ---------------------------------------------------------------------------
extern "C" void kernel_launch(void* const* d_in, const int* in_sizes, int n_in,
                              void* d_out, int out_size)
{
    const float* X    = (const float*)d_in[0];
    const float* mask = (const float*)d_in[1];
    const float* Wq   = (const float*)d_in[2];
    const float* bq   = (const float*)d_in[3];
    const float* Wk   = (const float*)d_in[4];
    const float* bk   = (const float*)d_in[5];
    const float* Wv   = (const float*)d_in[6];
    const float* bv   = (const float*)d_in[7];
    float* out = (float*)d_out;

    float *dQ, *dK, *dV;
    cudaGetSymbolAddress((void**)&dQ, g_Q);
    cudaGetSymbolAddress((void**)&dK, g_K);
    cudaGetSymbolAddress((void**)&dV, g_V);

    cudaFuncSetAttribute(qkv_gemm3, cudaFuncAttributeMaxDynamicSharedMemorySize, GEMM_SMEM);
    const int attn_smem = ATTN_WORDS * 4;
    cudaFuncSetAttribute(attn_f16, cudaFuncAttributeMaxDynamicSharedMemorySize, attn_smem);

    dim3 ggrid(HID / 128, M_ / 128, 3);   // (8, 64, 3)
    qkv_gemm3<<<ggrid, 256, GEMM_SMEM>>>(X, Wq, Wk, Wv, bq, bk, bv, dQ, dK, dV);

    attn_f16<<<PGRID, 128, attn_smem>>>(dQ, dK, dV, mask, out);
}

// round 11
// speedup vs baseline: 1.1043x; 1.1043x over previous
#include <cuda_runtime.h>
#include <cuda_bf16.h>
#include <cstdint>

#define B_   4
#define S_   2048
#define H_   16
#define D_   64
#define HID  1024
#define M_   (B_ * S_)

#define LOG2E 1.4426950408889634f

// Q,K stored PACKED fp16x2 dpairs: [B,H,S,32] u32. V stays f32 [B,H,S,64].
__device__ uint32_t g_Qh[B_ * H_ * S_ * 32];
__device__ uint32_t g_Kh[B_ * H_ * S_ * 32];
__device__ float    g_V [B_ * H_ * S_ * D_];

__device__ __forceinline__ uint32_t pack_f16x2(float lo, float hi) {
    uint32_t r;
    asm("cvt.rn.f16x2.f32 %0, %1, %2;" : "=r"(r) : "f"(hi), "f"(lo));
    return r;
}
__device__ __forceinline__ float ex2(float x) {
    float r;
    asm("ex2.approx.f32 %0, %1;" : "=f"(r) : "f"(x));
    return r;
}
__device__ __forceinline__ uint32_t smem_u32(const void* p) {
    uint32_t a;
    asm("{ .reg .u64 t; cvta.to.shared.u64 t, %1; cvt.u32.u64 %0, t; }" : "=r"(a) : "l"(p));
    return a;
}
__device__ __forceinline__ void cp16(uint32_t saddr, const void* gptr) {
    asm volatile("cp.async.ca.shared.global [%0], [%1], 16;" :: "r"(saddr), "l"(gptr));
}
#define CP_COMMIT() asm volatile("cp.async.commit_group;" ::: "memory")
#define CP_WAIT0()  asm volatile("cp.async.wait_group 0;" ::: "memory")

#define MMA_F16(c, a, b)                                               \
    asm volatile(                                                      \
        "mma.sync.aligned.m16n8k16.row.col.f32.f16.f16.f32 "           \
        "{%0,%1,%2,%3}, {%4,%5,%6,%7}, {%8,%9}, {%0,%1,%2,%3};\n"      \
        : "+f"((c)[0]), "+f"((c)[1]), "+f"((c)[2]), "+f"((c)[3])       \
        : "r"((a)[0]), "r"((a)[1]), "r"((a)[2]), "r"((a)[3]),          \
          "r"((b)[0]), "r"((b)[1]))

// ---------------------------------------------------------------------------
// Kernel A: fused QKV GEMM in fp16. Q/K outputs packed f16x2 (Q pre-scaled
// by 0.125*log2e), V output f32. Mainloop unchanged from R8/R9.
// ---------------------------------------------------------------------------
#define AH_S 20
#define BP_S 136
#define AH_W (128 * AH_S)
#define BP_W (16 * BP_S)
#define STG_W (AH_W + BP_W)
#define GEMM_SMEM (2 * STG_W * 4)

__global__ __launch_bounds__(256) void qkv_gemm3(const float* __restrict__ X,
                                                 const float* __restrict__ Wq,
                                                 const float* __restrict__ Wk,
                                                 const float* __restrict__ Wv,
                                                 const float* __restrict__ bq,
                                                 const float* __restrict__ bk,
                                                 const float* __restrict__ bv,
                                                 uint32_t* __restrict__ oQ,
                                                 uint32_t* __restrict__ oK,
                                                 float* __restrict__ oV)
{
    extern __shared__ uint32_t smg[];

    const int z = blockIdx.z;
    const float* W    = (z == 0) ? Wq : (z == 1) ? Wk : Wv;
    const float* bias = (z == 0) ? bq : (z == 1) ? bk : bv;

    const int tid  = threadIdx.x;
    const int warp = tid >> 5;
    const int lane = tid & 31;
    const int grp  = lane >> 2;
    const int thr  = lane & 3;
    const int wm   = warp >> 2;
    const int wn   = warp & 3;
    const int m0   = blockIdx.y * 128;
    const int n0   = blockIdx.x * 128;

    float acc[4][4][4];
    #pragma unroll
    for (int mt = 0; mt < 4; ++mt)
        #pragma unroll
        for (int nt = 0; nt < 4; ++nt)
            #pragma unroll
            for (int r = 0; r < 4; ++r) acc[mt][nt][r] = 0.f;

    float4 avr[4], b0r[2], b1r[2];
    #pragma unroll
    for (int t = 0; t < 4; ++t) {
        int i = tid + t * 256;
        int row = i >> 3, q = i & 7;
        avr[t] = *reinterpret_cast<const float4*>(&X[(size_t)(m0 + row) * HID + q * 4]);
    }
    #pragma unroll
    for (int t = 0; t < 2; ++t) {
        int i = tid + t * 256;
        int kp = i >> 5, n4 = (i & 31) * 4;
        b0r[t] = *reinterpret_cast<const float4*>(&W[(size_t)(2 * kp)     * HID + n0 + n4]);
        b1r[t] = *reinterpret_cast<const float4*>(&W[(size_t)(2 * kp + 1) * HID + n0 + n4]);
    }
    #pragma unroll
    for (int t = 0; t < 4; ++t) {
        int i = tid + t * 256;
        int row = i >> 3, q = i & 7;
        uint2 u = {pack_f16x2(avr[t].x, avr[t].y), pack_f16x2(avr[t].z, avr[t].w)};
        *reinterpret_cast<uint2*>(&smg[row * AH_S + 2 * q]) = u;
    }
    #pragma unroll
    for (int t = 0; t < 2; ++t) {
        int i = tid + t * 256;
        int kp = i >> 5, n4 = (i & 31) * 4;
        uint4 u = {pack_f16x2(b0r[t].x, b1r[t].x), pack_f16x2(b0r[t].y, b1r[t].y),
                   pack_f16x2(b0r[t].z, b1r[t].z), pack_f16x2(b0r[t].w, b1r[t].w)};
        *reinterpret_cast<uint4*>(&smg[AH_W + kp * BP_S + n4]) = u;
    }
    __syncthreads();

    for (int i = 0; i < 32; ++i) {
        const uint32_t* Ah = smg + (i & 1) * STG_W;
        const uint32_t* Bp = Ah + AH_W;
        if (i + 1 < 32) {
            const int kn = (i + 1) * 32;
            #pragma unroll
            for (int t = 0; t < 4; ++t) {
                int ii = tid + t * 256;
                int row = ii >> 3, q = ii & 7;
                avr[t] = *reinterpret_cast<const float4*>(&X[(size_t)(m0 + row) * HID + kn + q * 4]);
            }
            #pragma unroll
            for (int t = 0; t < 2; ++t) {
                int ii = tid + t * 256;
                int kp = ii >> 5, n4 = (ii & 31) * 4;
                b0r[t] = *reinterpret_cast<const float4*>(&W[(size_t)(kn + 2 * kp)     * HID + n0 + n4]);
                b1r[t] = *reinterpret_cast<const float4*>(&W[(size_t)(kn + 2 * kp + 1) * HID + n0 + n4]);
            }
        }
        #pragma unroll
        for (int s = 0; s < 2; ++s) {
            uint32_t a[4][4], b[4][2];
            #pragma unroll
            for (int mt = 0; mt < 4; ++mt) {
                int r = wm * 64 + mt * 16 + grp;
                a[mt][0] = Ah[r * AH_S + s * 8 + thr];
                a[mt][1] = Ah[(r + 8) * AH_S + s * 8 + thr];
                a[mt][2] = Ah[r * AH_S + s * 8 + 4 + thr];
                a[mt][3] = Ah[(r + 8) * AH_S + s * 8 + 4 + thr];
            }
            #pragma unroll
            for (int nt = 0; nt < 4; ++nt) {
                int c = wn * 32 + nt * 8 + grp;
                b[nt][0] = Bp[(s * 8 + thr)     * BP_S + c];
                b[nt][1] = Bp[(s * 8 + thr + 4) * BP_S + c];
            }
            #pragma unroll
            for (int mt = 0; mt < 4; ++mt)
                #pragma unroll
                for (int nt = 0; nt < 4; ++nt)
                    MMA_F16(acc[mt][nt], a[mt], b[nt]);
        }
        if (i + 1 < 32) {
            uint32_t* Ad = smg + ((i + 1) & 1) * STG_W;
            uint32_t* Bd = Ad + AH_W;
            #pragma unroll
            for (int t = 0; t < 4; ++t) {
                int ii = tid + t * 256;
                int row = ii >> 3, q = ii & 7;
                uint2 u = {pack_f16x2(avr[t].x, avr[t].y), pack_f16x2(avr[t].z, avr[t].w)};
                *reinterpret_cast<uint2*>(&Ad[row * AH_S + 2 * q]) = u;
            }
            #pragma unroll
            for (int t = 0; t < 2; ++t) {
                int ii = tid + t * 256;
                int kp = ii >> 5, n4 = (ii & 31) * 4;
                uint4 u = {pack_f16x2(b0r[t].x, b1r[t].x), pack_f16x2(b0r[t].y, b1r[t].y),
                           pack_f16x2(b0r[t].z, b1r[t].z), pack_f16x2(b0r[t].w, b1r[t].w)};
                *reinterpret_cast<uint4*>(&Bd[kp * BP_S + n4]) = u;
            }
        }
        __syncthreads();
    }

    // Epilogue
    const float qsc = 0.125f * LOG2E;
    #pragma unroll
    for (int mt = 0; mt < 4; ++mt) {
        #pragma unroll
        for (int nt = 0; nt < 4; ++nt) {
            #pragma unroll
            for (int half = 0; half < 2; ++half) {
                int m = m0 + wm * 64 + mt * 16 + grp + half * 8;
                int bb = m >> 11, s = m & 2047;
                int n = n0 + wn * 32 + nt * 8 + 2 * thr;
                int h = n >> 6, d = n & 63;
                float vx = acc[mt][nt][half * 2 + 0] + bias[n];
                float vy = acc[mt][nt][half * 2 + 1] + bias[n + 1];
                size_t rowbase = ((size_t)(bb * H_ + h) * S_) + s;
                if (z == 2) {
                    *reinterpret_cast<float2*>(&oV[rowbase * D_ + d]) = make_float2(vx, vy);
                } else if (z == 0) {
                    oQ[rowbase * 32 + (d >> 1)] = pack_f16x2(vx * qsc, vy * qsc);
                } else {
                    oK[rowbase * 32 + (d >> 1)] = pack_f16x2(vx, vy);
                }
            }
        }
    }
}

// ---------------------------------------------------------------------------
// Kernel B: flash attention, all-fp16 mma, exp2 softmax, ONE sync per tile.
// Q/K arrive pre-packed fp16 -> cp.async straight into mma layout.
// V double-buffered, staged one tile ahead from prefetch regs.
// ---------------------------------------------------------------------------
#define QH 36     // Q: [128 rows][32 dpairs]+pad
#define KP 36     // K: [64 keys][32 dpairs]+pad
#define VP 72     // V: [32 kpairs][64 d]+pad
#define QW2     (128 * QH)                 // 4608
#define OFF_KP0 QW2                        // 4608
#define OFF_KP1 (QW2 + 64 * KP)            // 6912
#define OFF_V0  (OFF_KP1 + 64 * KP)        // 9216
#define OFF_V1  (OFF_V0 + 32 * VP)         // 11520
#define OFF_M0  (OFF_V1 + 32 * VP)         // 13824
#define OFF_M1  (OFF_M0 + 64)              // 13888
#define ATTN_WORDS (OFF_M1 + 64)           // 13952 words = 55808 B

__global__ __launch_bounds__(128) void attn_f16(const uint32_t* __restrict__ Qh,
                                                const uint32_t* __restrict__ Kh,
                                                const float* __restrict__ V,
                                                const float* __restrict__ mask,
                                                float* __restrict__ out)
{
    extern __shared__ uint32_t sm[];
    const uint32_t sbase = smem_u32(sm);

    const int tid  = threadIdx.x;
    const int warp = tid >> 5;
    const int lane = tid & 31;
    const int grp  = lane >> 2;
    const int thr  = lane & 3;
    const int q0   = blockIdx.x * 128;
    const int h    = blockIdx.y;
    const int b    = blockIdx.z;
    const size_t pbase = (size_t)(b * H_ + h) * S_ * 32;   // packed Q/K
    const size_t vbase = (size_t)(b * H_ + h) * S_ * D_;   // f32 V
    const int wr0 = warp * 32;

    // ---- prologue: cp.async Q (packed) + K tile0 + mask0 ----
    #pragma unroll
    for (int t = 0; t < 8; ++t) {                 // Q: 1024 16B-chunks
        int i = tid + t * 128;
        int r = i >> 3, c4 = (i & 7) * 4;
        cp16(sbase + (r * QH + c4) * 4, &Qh[pbase + (size_t)(q0 + r) * 32 + c4]);
    }
    #pragma unroll
    for (int t = 0; t < 4; ++t) {                 // K: 512 chunks
        int i = tid + t * 128;
        int r = i >> 3, c4 = (i & 7) * 4;
        cp16(sbase + (OFF_KP0 + r * KP + c4) * 4, &Kh[pbase + (size_t)r * 32 + c4]);
    }
    if (tid < 16) cp16(sbase + (OFF_M0 + tid * 4) * 4, &mask[b * S_ + tid * 4]);
    CP_COMMIT();

    // stage V(0) into Vp0 (no readers yet), then prefetch V(1)
    float4 vr[8];
    #pragma unroll
    for (int t = 0; t < 4; ++t) {
        int i = tid + t * 128;
        int r2 = i >> 4, c = (i & 15) * 4;
        float4 v0 = *reinterpret_cast<const float4*>(&V[vbase + (size_t)(2 * r2)     * D_ + c]);
        float4 v1 = *reinterpret_cast<const float4*>(&V[vbase + (size_t)(2 * r2 + 1) * D_ + c]);
        uint4 u = {pack_f16x2(v0.x, v1.x), pack_f16x2(v0.y, v1.y),
                   pack_f16x2(v0.z, v1.z), pack_f16x2(v0.w, v1.w)};
        *reinterpret_cast<uint4*>(&sm[OFF_V0 + r2 * VP + c]) = u;
    }
    #pragma unroll
    for (int t = 0; t < 4; ++t) {
        int i = tid + t * 128;
        int r2 = i >> 4, c = (i & 15) * 4;
        vr[2 * t]     = *reinterpret_cast<const float4*>(&V[vbase + (size_t)(64 + 2 * r2)     * D_ + c]);
        vr[2 * t + 1] = *reinterpret_cast<const float4*>(&V[vbase + (size_t)(64 + 2 * r2 + 1) * D_ + c]);
    }

    float mrun[4] = {-1e30f, -1e30f, -1e30f, -1e30f};
    float lrun[4] = {0.f, 0.f, 0.f, 0.f};
    float o[2][8][4];
    #pragma unroll
    for (int at = 0; at < 2; ++at)
        #pragma unroll
        for (int nt = 0; nt < 8; ++nt)
            #pragma unroll
            for (int r = 0; r < 4; ++r) o[at][nt][r] = 0.f;

    for (int it = 0; it < 32; ++it) {
        const int bu = it & 1;
        const uint32_t kpo = bu ? OFF_KP1 : OFF_KP0;
        const uint32_t vpo = bu ? OFF_V1  : OFF_V0;
        const float* msk = (const float*)(sm + (bu ? OFF_M1 : OFF_M0));

        CP_WAIT0();
        __syncthreads();   // K(it)/mask(it) arrived; V(it) staged; compute(it-1) done

        if (it + 1 < 32) {
            const int kn = (it + 1) * 64;
            const uint32_t kdo = bu ? OFF_KP0 : OFF_KP1;
            #pragma unroll
            for (int t = 0; t < 4; ++t) {
                int i = tid + t * 128;
                int r = i >> 3, c4 = (i & 7) * 4;
                cp16(sbase + (kdo + r * KP + c4) * 4,
                     &Kh[pbase + (size_t)(kn + r) * 32 + c4]);
            }
            if (tid < 16)
                cp16(sbase + ((bu ? OFF_M0 : OFF_M1) + tid * 4) * 4,
                     &mask[b * S_ + kn + tid * 4]);
            CP_COMMIT();
            // stage V(it+1) into the buffer compute(it-1) just released
            const uint32_t vdo = bu ? OFF_V0 : OFF_V1;
            #pragma unroll
            for (int t = 0; t < 4; ++t) {
                int i = tid + t * 128;
                int r2 = i >> 4, c = (i & 15) * 4;
                float4 v0 = vr[2 * t], v1 = vr[2 * t + 1];
                uint4 u = {pack_f16x2(v0.x, v1.x), pack_f16x2(v0.y, v1.y),
                           pack_f16x2(v0.z, v1.z), pack_f16x2(v0.w, v1.w)};
                *reinterpret_cast<uint4*>(&sm[vdo + r2 * VP + c]) = u;
            }
            if (it + 2 < 32) {
                const int kn2 = (it + 2) * 64;
                #pragma unroll
                for (int t = 0; t < 4; ++t) {
                    int i = tid + t * 128;
                    int r2 = i >> 4, c = (i & 15) * 4;
                    vr[2 * t]     = *reinterpret_cast<const float4*>(&V[vbase + (size_t)(kn2 + 2 * r2)     * D_ + c]);
                    vr[2 * t + 1] = *reinterpret_cast<const float4*>(&V[vbase + (size_t)(kn2 + 2 * r2 + 1) * D_ + c]);
                }
            }
        }

        // ---- S = Q @ K^T (fp16 k16; log2-domain scores) ----
        float s[2][8][4];
        #pragma unroll
        for (int at = 0; at < 2; ++at)
            #pragma unroll
            for (int nt = 0; nt < 8; ++nt)
                #pragma unroll
                for (int r = 0; r < 4; ++r) s[at][nt][r] = 0.f;

        #pragma unroll
        for (int ks = 0; ks < 4; ++ks) {
            uint32_t bfr[8][2];
            #pragma unroll
            for (int nt = 0; nt < 8; ++nt) {
                int key = nt * 8 + grp;
                bfr[nt][0] = sm[kpo + key * KP + ks * 8 + thr];
                bfr[nt][1] = sm[kpo + key * KP + ks * 8 + 4 + thr];
            }
            #pragma unroll
            for (int at = 0; at < 2; ++at) {
                int r0 = wr0 + at * 16 + grp;
                uint32_t a[4];
                a[0] = sm[r0 * QH + ks * 8 + thr];
                a[1] = sm[(r0 + 8) * QH + ks * 8 + thr];
                a[2] = sm[r0 * QH + ks * 8 + 4 + thr];
                a[3] = sm[(r0 + 8) * QH + ks * 8 + 4 + thr];
                #pragma unroll
                for (int nt = 0; nt < 8; ++nt)
                    MMA_F16(s[at][nt], a, bfr[nt]);
            }
        }

        // ---- mask (log2e folded via fma) + online softmax; P -> f16x2 ----
        uint32_t pb[2][8][2];
        #pragma unroll
        for (int at = 0; at < 2; ++at) {
            float rmax0 = -1e30f, rmax1 = -1e30f;
            #pragma unroll
            for (int nt = 0; nt < 8; ++nt) {
                int c0 = nt * 8 + 2 * thr;
                float mk0 = msk[c0], mk1 = msk[c0 + 1];
                s[at][nt][0] = fmaf(mk0, LOG2E, s[at][nt][0]);
                s[at][nt][1] = fmaf(mk1, LOG2E, s[at][nt][1]);
                s[at][nt][2] = fmaf(mk0, LOG2E, s[at][nt][2]);
                s[at][nt][3] = fmaf(mk1, LOG2E, s[at][nt][3]);
                rmax0 = fmaxf(rmax0, fmaxf(s[at][nt][0], s[at][nt][1]));
                rmax1 = fmaxf(rmax1, fmaxf(s[at][nt][2], s[at][nt][3]));
            }
            rmax0 = fmaxf(rmax0, __shfl_xor_sync(0xffffffffu, rmax0, 1));
            rmax0 = fmaxf(rmax0, __shfl_xor_sync(0xffffffffu, rmax0, 2));
            rmax1 = fmaxf(rmax1, __shfl_xor_sync(0xffffffffu, rmax1, 1));
            rmax1 = fmaxf(rmax1, __shfl_xor_sync(0xffffffffu, rmax1, 2));

            const int g0 = at * 2, g1 = at * 2 + 1;
            const float mnew0 = fmaxf(mrun[g0], rmax0);
            const float mnew1 = fmaxf(mrun[g1], rmax1);
            float sum0 = 0.f, sum1 = 0.f;
            #pragma unroll
            for (int nt = 0; nt < 8; ++nt) {
                s[at][nt][0] = ex2(s[at][nt][0] - mnew0);
                s[at][nt][1] = ex2(s[at][nt][1] - mnew0);
                s[at][nt][2] = ex2(s[at][nt][2] - mnew1);
                s[at][nt][3] = ex2(s[at][nt][3] - mnew1);
                sum0 += s[at][nt][0] + s[at][nt][1];
                sum1 += s[at][nt][2] + s[at][nt][3];
                pb[at][nt][0] = pack_f16x2(s[at][nt][0], s[at][nt][1]);
                pb[at][nt][1] = pack_f16x2(s[at][nt][2], s[at][nt][3]);
            }
            sum0 += __shfl_xor_sync(0xffffffffu, sum0, 1);
            sum0 += __shfl_xor_sync(0xffffffffu, sum0, 2);
            sum1 += __shfl_xor_sync(0xffffffffu, sum1, 1);
            sum1 += __shfl_xor_sync(0xffffffffu, sum1, 2);

            const float cf0 = ex2(mrun[g0] - mnew0);
            const float cf1 = ex2(mrun[g1] - mnew1);
            mrun[g0] = mnew0;  lrun[g0] = lrun[g0] * cf0 + sum0;
            mrun[g1] = mnew1;  lrun[g1] = lrun[g1] * cf1 + sum1;

            #pragma unroll
            for (int nt = 0; nt < 8; ++nt) {
                o[at][nt][0] *= cf0;  o[at][nt][1] *= cf0;
                o[at][nt][2] *= cf1;  o[at][nt][3] *= cf1;
            }
        }

        // ---- O += P @ V (fp16 k16, A from registers) ----
        #pragma unroll
        for (int sstep = 0; sstep < 4; ++sstep) {
            uint32_t bfr[8][2];
            #pragma unroll
            for (int nt = 0; nt < 8; ++nt) {
                int d = nt * 8 + grp;
                bfr[nt][0] = sm[vpo + (sstep * 8 + thr)     * VP + d];
                bfr[nt][1] = sm[vpo + (sstep * 8 + thr + 4) * VP + d];
            }
            #pragma unroll
            for (int at = 0; at < 2; ++at) {
                uint32_t a[4] = {pb[at][2 * sstep][0], pb[at][2 * sstep][1],
                                 pb[at][2 * sstep + 1][0], pb[at][2 * sstep + 1][1]};
                #pragma unroll
                for (int nt = 0; nt < 8; ++nt)
                    MMA_F16(o[at][nt], a, bfr[nt]);
            }
        }
    }

    // Output: [B, S, H*Dh]
    #pragma unroll
    for (int at = 0; at < 2; ++at) {
        #pragma unroll
        for (int half = 0; half < 2; ++half) {
            const int g = at * 2 + half;
            const float inv = 1.f / lrun[g];
            const int q = q0 + wr0 + at * 16 + grp + half * 8;
            #pragma unroll
            for (int nt = 0; nt < 8; ++nt) {
                int d = nt * 8 + 2 * thr;
                float2 v = {o[at][nt][half * 2 + 0] * inv,
                            o[at][nt][half * 2 + 1] * inv};
                *reinterpret_cast<float2*>(
                    &out[((size_t)(b * S_ + q)) * HID + h * D_ + d]) = v;
            }
        }
    }
}

// ---------------------------------------------------------------------------
// Launch
// ---------------------------------------------------------------------------
extern "C" void kernel_launch(void* const* d_in, const int* in_sizes, int n_in,
                              void* d_out, int out_size)
{
    const float* X    = (const float*)d_in[0];
    const float* mask = (const float*)d_in[1];
    const float* Wq   = (const float*)d_in[2];
    const float* bq   = (const float*)d_in[3];
    const float* Wk   = (const float*)d_in[4];
    const float* bk   = (const float*)d_in[5];
    const float* Wv   = (const float*)d_in[6];
    const float* bv   = (const float*)d_in[7];
    float* out = (float*)d_out;

    uint32_t *dQ, *dK;
    float *dV;
    cudaGetSymbolAddress((void**)&dQ, g_Qh);
    cudaGetSymbolAddress((void**)&dK, g_Kh);
    cudaGetSymbolAddress((void**)&dV, g_V);

    cudaFuncSetAttribute(qkv_gemm3, cudaFuncAttributeMaxDynamicSharedMemorySize, GEMM_SMEM);
    const int attn_smem = ATTN_WORDS * 4;   // 55808 B
    cudaFuncSetAttribute(attn_f16, cudaFuncAttributeMaxDynamicSharedMemorySize, attn_smem);

    dim3 ggrid(HID / 128, M_ / 128, 3);   // (8, 64, 3)
    qkv_gemm3<<<ggrid, 256, GEMM_SMEM>>>(X, Wq, Wk, Wv, bq, bk, bv, dQ, dK, dV);

    dim3 agrid(S_ / 128, H_, B_);         // (16, 16, 4)
    attn_f16<<<agrid, 128, attn_smem>>>(dQ, dK, dV, mask, out);
}

// round 14
// speedup vs baseline: 1.1149x; 1.0096x over previous
#include <cuda_runtime.h>
#include <cuda_bf16.h>
#include <cstdint>

#define B_   4
#define S_   2048
#define H_   16
#define D_   64
#define HID  1024
#define M_   (B_ * S_)

#define LOG2E 1.4426950408889634f

// Q,K packed fp16x2 dpairs [B,H,S,32] u32 (Q pre-scaled by 0.125*log2e).
// V packed fp16x2 KEY-pairs [B,H,S/2,64] u32: Vp[kp][d] = (V[2kp][d], V[2kp+1][d]).
__device__ uint32_t g_Qh[B_ * H_ * S_ * 32];
__device__ uint32_t g_Kh[B_ * H_ * S_ * 32];
__device__ uint32_t g_Vp[B_ * H_ * (S_ / 2) * 64];

__device__ __forceinline__ uint32_t pack_f16x2(float lo, float hi) {
    uint32_t r;
    asm("cvt.rn.f16x2.f32 %0, %1, %2;" : "=r"(r) : "f"(hi), "f"(lo));
    return r;
}
__device__ __forceinline__ float ex2(float x) {
    float r;
    asm("ex2.approx.f32 %0, %1;" : "=f"(r) : "f"(x));
    return r;
}
__device__ __forceinline__ uint32_t smem_u32(const void* p) {
    uint32_t a;
    asm("{ .reg .u64 t; cvta.to.shared.u64 t, %1; cvt.u32.u64 %0, t; }" : "=r"(a) : "l"(p));
    return a;
}
__device__ __forceinline__ void cp16(uint32_t saddr, const void* gptr) {
    asm volatile("cp.async.ca.shared.global [%0], [%1], 16;" :: "r"(saddr), "l"(gptr));
}
#define CP_COMMIT() asm volatile("cp.async.commit_group;" ::: "memory")
#define CP_WAIT0()  asm volatile("cp.async.wait_group 0;" ::: "memory")

#define MMA_F16(c, a, b)                                               \
    asm volatile(                                                      \
        "mma.sync.aligned.m16n8k16.row.col.f32.f16.f16.f32 "           \
        "{%0,%1,%2,%3}, {%4,%5,%6,%7}, {%8,%9}, {%0,%1,%2,%3};\n"      \
        : "+f"((c)[0]), "+f"((c)[1]), "+f"((c)[2]), "+f"((c)[3])       \
        : "r"((a)[0]), "r"((a)[1]), "r"((a)[2]), "r"((a)[3]),          \
          "r"((b)[0]), "r"((b)[1]))

// ---------------------------------------------------------------------------
// Kernel A: fused QKV GEMM in fp16. Q/K packed dpairs; V packed KEY-pairs
// via shfl_xor(4) in the epilogue. Mainloop unchanged from R8-R11.
// ---------------------------------------------------------------------------
#define AH_S 20
#define BP_S 136
#define AH_W (128 * AH_S)
#define BP_W (16 * BP_S)
#define STG_W (AH_W + BP_W)
#define GEMM_SMEM (2 * STG_W * 4)

__global__ __launch_bounds__(256) void qkv_gemm3(const float* __restrict__ X,
                                                 const float* __restrict__ Wq,
                                                 const float* __restrict__ Wk,
                                                 const float* __restrict__ Wv,
                                                 const float* __restrict__ bq,
                                                 const float* __restrict__ bk,
                                                 const float* __restrict__ bv,
                                                 uint32_t* __restrict__ oQ,
                                                 uint32_t* __restrict__ oK,
                                                 uint32_t* __restrict__ oVp)
{
    extern __shared__ uint32_t smg[];

    const int z = blockIdx.z;
    const float* W    = (z == 0) ? Wq : (z == 1) ? Wk : Wv;
    const float* bias = (z == 0) ? bq : (z == 1) ? bk : bv;

    const int tid  = threadIdx.x;
    const int warp = tid >> 5;
    const int lane = tid & 31;
    const int grp  = lane >> 2;
    const int thr  = lane & 3;
    const int wm   = warp >> 2;
    const int wn   = warp & 3;
    const int m0   = blockIdx.y * 128;
    const int n0   = blockIdx.x * 128;

    float acc[4][4][4];
    #pragma unroll
    for (int mt = 0; mt < 4; ++mt)
        #pragma unroll
        for (int nt = 0; nt < 4; ++nt)
            #pragma unroll
            for (int r = 0; r < 4; ++r) acc[mt][nt][r] = 0.f;

    float4 avr[4], b0r[2], b1r[2];
    #pragma unroll
    for (int t = 0; t < 4; ++t) {
        int i = tid + t * 256;
        int row = i >> 3, q = i & 7;
        avr[t] = *reinterpret_cast<const float4*>(&X[(size_t)(m0 + row) * HID + q * 4]);
    }
    #pragma unroll
    for (int t = 0; t < 2; ++t) {
        int i = tid + t * 256;
        int kp = i >> 5, n4 = (i & 31) * 4;
        b0r[t] = *reinterpret_cast<const float4*>(&W[(size_t)(2 * kp)     * HID + n0 + n4]);
        b1r[t] = *reinterpret_cast<const float4*>(&W[(size_t)(2 * kp + 1) * HID + n0 + n4]);
    }
    #pragma unroll
    for (int t = 0; t < 4; ++t) {
        int i = tid + t * 256;
        int row = i >> 3, q = i & 7;
        uint2 u = {pack_f16x2(avr[t].x, avr[t].y), pack_f16x2(avr[t].z, avr[t].w)};
        *reinterpret_cast<uint2*>(&smg[row * AH_S + 2 * q]) = u;
    }
    #pragma unroll
    for (int t = 0; t < 2; ++t) {
        int i = tid + t * 256;
        int kp = i >> 5, n4 = (i & 31) * 4;
        uint4 u = {pack_f16x2(b0r[t].x, b1r[t].x), pack_f16x2(b0r[t].y, b1r[t].y),
                   pack_f16x2(b0r[t].z, b1r[t].z), pack_f16x2(b0r[t].w, b1r[t].w)};
        *reinterpret_cast<uint4*>(&smg[AH_W + kp * BP_S + n4]) = u;
    }
    __syncthreads();

    for (int i = 0; i < 32; ++i) {
        const uint32_t* Ah = smg + (i & 1) * STG_W;
        const uint32_t* Bp = Ah + AH_W;
        if (i + 1 < 32) {
            const int kn = (i + 1) * 32;
            #pragma unroll
            for (int t = 0; t < 4; ++t) {
                int ii = tid + t * 256;
                int row = ii >> 3, q = ii & 7;
                avr[t] = *reinterpret_cast<const float4*>(&X[(size_t)(m0 + row) * HID + kn + q * 4]);
            }
            #pragma unroll
            for (int t = 0; t < 2; ++t) {
                int ii = tid + t * 256;
                int kp = ii >> 5, n4 = (ii & 31) * 4;
                b0r[t] = *reinterpret_cast<const float4*>(&W[(size_t)(kn + 2 * kp)     * HID + n0 + n4]);
                b1r[t] = *reinterpret_cast<const float4*>(&W[(size_t)(kn + 2 * kp + 1) * HID + n0 + n4]);
            }
        }
        #pragma unroll
        for (int s = 0; s < 2; ++s) {
            uint32_t a[4][4], b[4][2];
            #pragma unroll
            for (int mt = 0; mt < 4; ++mt) {
                int r = wm * 64 + mt * 16 + grp;
                a[mt][0] = Ah[r * AH_S + s * 8 + thr];
                a[mt][1] = Ah[(r + 8) * AH_S + s * 8 + thr];
                a[mt][2] = Ah[r * AH_S + s * 8 + 4 + thr];
                a[mt][3] = Ah[(r + 8) * AH_S + s * 8 + 4 + thr];
            }
            #pragma unroll
            for (int nt = 0; nt < 4; ++nt) {
                int c = wn * 32 + nt * 8 + grp;
                b[nt][0] = Bp[(s * 8 + thr)     * BP_S + c];
                b[nt][1] = Bp[(s * 8 + thr + 4) * BP_S + c];
            }
            #pragma unroll
            for (int mt = 0; mt < 4; ++mt)
                #pragma unroll
                for (int nt = 0; nt < 4; ++nt)
                    MMA_F16(acc[mt][nt], a[mt], b[nt]);
        }
        if (i + 1 < 32) {
            uint32_t* Ad = smg + ((i + 1) & 1) * STG_W;
            uint32_t* Bd = Ad + AH_W;
            #pragma unroll
            for (int t = 0; t < 4; ++t) {
                int ii = tid + t * 256;
                int row = ii >> 3, q = ii & 7;
                uint2 u = {pack_f16x2(avr[t].x, avr[t].y), pack_f16x2(avr[t].z, avr[t].w)};
                *reinterpret_cast<uint2*>(&Ad[row * AH_S + 2 * q]) = u;
            }
            #pragma unroll
            for (int t = 0; t < 2; ++t) {
                int ii = tid + t * 256;
                int kp = ii >> 5, n4 = (ii & 31) * 4;
                uint4 u = {pack_f16x2(b0r[t].x, b1r[t].x), pack_f16x2(b0r[t].y, b1r[t].y),
                           pack_f16x2(b0r[t].z, b1r[t].z), pack_f16x2(b0r[t].w, b1r[t].w)};
                *reinterpret_cast<uint4*>(&Bd[kp * BP_S + n4]) = u;
            }
        }
        __syncthreads();
    }

    // Epilogue
    const float qsc = 0.125f * LOG2E;
    #pragma unroll
    for (int mt = 0; mt < 4; ++mt) {
        #pragma unroll
        for (int nt = 0; nt < 4; ++nt) {
            #pragma unroll
            for (int half = 0; half < 2; ++half) {
                int m = m0 + wm * 64 + mt * 16 + grp + half * 8;
                int bb = m >> 11, s = m & 2047;
                int n = n0 + wn * 32 + nt * 8 + 2 * thr;
                int h = n >> 6, d = n & 63;
                float vx = acc[mt][nt][half * 2 + 0] + bias[n];
                float vy = acc[mt][nt][half * 2 + 1] + bias[n + 1];
                size_t rowbase = ((size_t)(bb * H_ + h) * S_) + s;
                if (z == 2) {
                    // pair adjacent keys (m even <-> grp even); partner = lane^4
                    float px = __shfl_xor_sync(0xffffffffu, vx, 4);
                    float py = __shfl_xor_sync(0xffffffffu, vy, 4);
                    if ((grp & 1) == 0) {
                        uint2 u = {pack_f16x2(vx, px), pack_f16x2(vy, py)};
                        *reinterpret_cast<uint2*>(
                            &oVp[(((size_t)(bb * H_ + h) * (S_ / 2)) + (s >> 1)) * 64 + d]) = u;
                    }
                } else if (z == 0) {
                    oQ[rowbase * 32 + (d >> 1)] = pack_f16x2(vx * qsc, vy * qsc);
                } else {
                    oK[rowbase * 32 + (d >> 1)] = pack_f16x2(vx, vy);
                }
            }
        }
    }
}

// ---------------------------------------------------------------------------
// Kernel B: flash attention. ALL operands arrive pre-packed fp16 -> staging
// is pure cp.async (K, V, mask double-buffered), one sync per tile.
// ---------------------------------------------------------------------------
#define QH 36     // Q: [128 rows][32 dpairs]+pad
#define KP 36     // K: [64 keys][32 dpairs]+pad
#define VP 72     // V: [32 kpairs][64 d]+pad
#define QW2     (128 * QH)                 // 4608
#define OFF_KP0 QW2
#define OFF_KP1 (QW2 + 64 * KP)
#define OFF_V0  (OFF_KP1 + 64 * KP)
#define OFF_V1  (OFF_V0 + 32 * VP)
#define OFF_M0  (OFF_V1 + 32 * VP)
#define OFF_M1  (OFF_M0 + 64)
#define ATTN_WORDS (OFF_M1 + 64)           // 13952 words = 55808 B

__global__ __launch_bounds__(128) void attn_f16(const uint32_t* __restrict__ Qh,
                                                const uint32_t* __restrict__ Kh,
                                                const uint32_t* __restrict__ Vp,
                                                const float* __restrict__ mask,
                                                float* __restrict__ out)
{
    extern __shared__ uint32_t sm[];
    const uint32_t sbase = smem_u32(sm);

    const int tid  = threadIdx.x;
    const int warp = tid >> 5;
    const int lane = tid & 31;
    const int grp  = lane >> 2;
    const int thr  = lane & 3;
    const int q0   = blockIdx.x * 128;
    const int h    = blockIdx.y;
    const int b    = blockIdx.z;
    const size_t pbase = (size_t)(b * H_ + h) * S_ * 32;        // packed Q/K
    const size_t vpb   = (size_t)(b * H_ + h) * (S_ / 2) * 64;  // packed V
    const int wr0 = warp * 32;

    // ---- prologue: cp.async Q + K(0) + V(0) + mask(0) ----
    #pragma unroll
    for (int t = 0; t < 8; ++t) {
        int i = tid + t * 128;
        int r = i >> 3, c4 = (i & 7) * 4;
        cp16(sbase + (r * QH + c4) * 4, &Qh[pbase + (size_t)(q0 + r) * 32 + c4]);
    }
    #pragma unroll
    for (int t = 0; t < 4; ++t) {
        int i = tid + t * 128;
        int r = i >> 3, c4 = (i & 7) * 4;
        cp16(sbase + (OFF_KP0 + r * KP + c4) * 4, &Kh[pbase + (size_t)r * 32 + c4]);
    }
    #pragma unroll
    for (int t = 0; t < 4; ++t) {
        int i = tid + t * 128;
        int r2 = i >> 4, c4 = (i & 15) * 4;
        cp16(sbase + (OFF_V0 + r2 * VP + c4) * 4, &Vp[vpb + (size_t)r2 * 64 + c4]);
    }
    if (tid < 16) cp16(sbase + (OFF_M0 + tid * 4) * 4, &mask[b * S_ + tid * 4]);
    CP_COMMIT();

    float mrun[4] = {-1e30f, -1e30f, -1e30f, -1e30f};
    float lrun[4] = {0.f, 0.f, 0.f, 0.f};
    float o[2][8][4];
    #pragma unroll
    for (int at = 0; at < 2; ++at)
        #pragma unroll
        for (int nt = 0; nt < 8; ++nt)
            #pragma unroll
            for (int r = 0; r < 4; ++r) o[at][nt][r] = 0.f;

    for (int it = 0; it < 32; ++it) {
        const int bu = it & 1;
        const uint32_t kpo = bu ? OFF_KP1 : OFF_KP0;
        const uint32_t vpo = bu ? OFF_V1  : OFF_V0;
        const float* msk = (const float*)(sm + (bu ? OFF_M1 : OFF_M0));

        CP_WAIT0();
        __syncthreads();   // tile it data in smem; compute(it-1) done (buffers free)

        if (it + 1 < 32) {
            const int kn = (it + 1) * 64;
            const uint32_t kdo = bu ? OFF_KP0 : OFF_KP1;
            const uint32_t vdo = bu ? OFF_V0  : OFF_V1;
            #pragma unroll
            for (int t = 0; t < 4; ++t) {
                int i = tid + t * 128;
                int r = i >> 3, c4 = (i & 7) * 4;
                cp16(sbase + (kdo + r * KP + c4) * 4,
                     &Kh[pbase + (size_t)(kn + r) * 32 + c4]);
            }
            #pragma unroll
            for (int t = 0; t < 4; ++t) {
                int i = tid + t * 128;
                int r2 = i >> 4, c4 = (i & 15) * 4;
                cp16(sbase + (vdo + r2 * VP + c4) * 4,
                     &Vp[vpb + (size_t)((it + 1) * 32 + r2) * 64 + c4]);
            }
            if (tid < 16)
                cp16(sbase + ((bu ? OFF_M0 : OFF_M1) + tid * 4) * 4,
                     &mask[b * S_ + kn + tid * 4]);
            CP_COMMIT();
        }

        // ---- S = Q @ K^T (fp16 k16; log2-domain scores) ----
        float s[2][8][4];
        #pragma unroll
        for (int at = 0; at < 2; ++at)
            #pragma unroll
            for (int nt = 0; nt < 8; ++nt)
                #pragma unroll
                for (int r = 0; r < 4; ++r) s[at][nt][r] = 0.f;

        #pragma unroll
        for (int ks = 0; ks < 4; ++ks) {
            uint32_t bfr[8][2];
            #pragma unroll
            for (int nt = 0; nt < 8; ++nt) {
                int key = nt * 8 + grp;
                bfr[nt][0] = sm[kpo + key * KP + ks * 8 + thr];
                bfr[nt][1] = sm[kpo + key * KP + ks * 8 + 4 + thr];
            }
            #pragma unroll
            for (int at = 0; at < 2; ++at) {
                int r0 = wr0 + at * 16 + grp;
                uint32_t a[4];
                a[0] = sm[r0 * QH + ks * 8 + thr];
                a[1] = sm[(r0 + 8) * QH + ks * 8 + thr];
                a[2] = sm[r0 * QH + ks * 8 + 4 + thr];
                a[3] = sm[(r0 + 8) * QH + ks * 8 + 4 + thr];
                #pragma unroll
                for (int nt = 0; nt < 8; ++nt)
                    MMA_F16(s[at][nt], a, bfr[nt]);
            }
        }

        // ---- mask (log2e via fma) + online softmax (base-2); P -> f16x2 ----
        uint32_t pb[2][8][2];
        #pragma unroll
        for (int at = 0; at < 2; ++at) {
            float rmax0 = -1e30f, rmax1 = -1e30f;
            #pragma unroll
            for (int nt = 0; nt < 8; ++nt) {
                int c0 = nt * 8 + 2 * thr;
                float mk0 = msk[c0], mk1 = msk[c0 + 1];
                s[at][nt][0] = fmaf(mk0, LOG2E, s[at][nt][0]);
                s[at][nt][1] = fmaf(mk1, LOG2E, s[at][nt][1]);
                s[at][nt][2] = fmaf(mk0, LOG2E, s[at][nt][2]);
                s[at][nt][3] = fmaf(mk1, LOG2E, s[at][nt][3]);
                rmax0 = fmaxf(rmax0, fmaxf(s[at][nt][0], s[at][nt][1]));
                rmax1 = fmaxf(rmax1, fmaxf(s[at][nt][2], s[at][nt][3]));
            }
            rmax0 = fmaxf(rmax0, __shfl_xor_sync(0xffffffffu, rmax0, 1));
            rmax0 = fmaxf(rmax0, __shfl_xor_sync(0xffffffffu, rmax0, 2));
            rmax1 = fmaxf(rmax1, __shfl_xor_sync(0xffffffffu, rmax1, 1));
            rmax1 = fmaxf(rmax1, __shfl_xor_sync(0xffffffffu, rmax1, 2));

            const int g0 = at * 2, g1 = at * 2 + 1;
            const float mnew0 = fmaxf(mrun[g0], rmax0);
            const float mnew1 = fmaxf(mrun[g1], rmax1);
            float sum0 = 0.f, sum1 = 0.f;
            #pragma unroll
            for (int nt = 0; nt < 8; ++nt) {
                s[at][nt][0] = ex2(s[at][nt][0] - mnew0);
                s[at][nt][1] = ex2(s[at][nt][1] - mnew0);
                s[at][nt][2] = ex2(s[at][nt][2] - mnew1);
                s[at][nt][3] = ex2(s[at][nt][3] - mnew1);
                sum0 += s[at][nt][0] + s[at][nt][1];
                sum1 += s[at][nt][2] + s[at][nt][3];
                pb[at][nt][0] = pack_f16x2(s[at][nt][0], s[at][nt][1]);
                pb[at][nt][1] = pack_f16x2(s[at][nt][2], s[at][nt][3]);
            }
            sum0 += __shfl_xor_sync(0xffffffffu, sum0, 1);
            sum0 += __shfl_xor_sync(0xffffffffu, sum0, 2);
            sum1 += __shfl_xor_sync(0xffffffffu, sum1, 1);
            sum1 += __shfl_xor_sync(0xffffffffu, sum1, 2);

            const float cf0 = ex2(mrun[g0] - mnew0);
            const float cf1 = ex2(mrun[g1] - mnew1);
            mrun[g0] = mnew0;  lrun[g0] = lrun[g0] * cf0 + sum0;
            mrun[g1] = mnew1;  lrun[g1] = lrun[g1] * cf1 + sum1;

            #pragma unroll
            for (int nt = 0; nt < 8; ++nt) {
                o[at][nt][0] *= cf0;  o[at][nt][1] *= cf0;
                o[at][nt][2] *= cf1;  o[at][nt][3] *= cf1;
            }
        }

        // ---- O += P @ V (fp16 k16, A from registers) ----
        #pragma unroll
        for (int sstep = 0; sstep < 4; ++sstep) {
            uint32_t bfr[8][2];
            #pragma unroll
            for (int nt = 0; nt < 8; ++nt) {
                int d = nt * 8 + grp;
                bfr[nt][0] = sm[vpo + (sstep * 8 + thr)     * VP + d];
                bfr[nt][1] = sm[vpo + (sstep * 8 + thr + 4) * VP + d];
            }
            #pragma unroll
            for (int at = 0; at < 2; ++at) {
                uint32_t a[4] = {pb[at][2 * sstep][0], pb[at][2 * sstep][1],
                                 pb[at][2 * sstep + 1][0], pb[at][2 * sstep + 1][1]};
                #pragma unroll
                for (int nt = 0; nt < 8; ++nt)
                    MMA_F16(o[at][nt], a, bfr[nt]);
            }
        }
    }

    // Output: [B, S, H*Dh]
    #pragma unroll
    for (int at = 0; at < 2; ++at) {
        #pragma unroll
        for (int half = 0; half < 2; ++half) {
            const int g = at * 2 + half;
            const float inv = 1.f / lrun[g];
            const int q = q0 + wr0 + at * 16 + grp + half * 8;
            #pragma unroll
            for (int nt = 0; nt < 8; ++nt) {
                int d = nt * 8 + 2 * thr;
                float2 v = {o[at][nt][half * 2 + 0] * inv,
                            o[at][nt][half * 2 + 1] * inv};
                *reinterpret_cast<float2*>(
                    &out[((size_t)(b * S_ + q)) * HID + h * D_ + d]) = v;
            }
        }
    }
}

// ---------------------------------------------------------------------------
// Launch
// ---------------------------------------------------------------------------
extern "C" void kernel_launch(void* const* d_in, const int* in_sizes, int n_in,
                              void* d_out, int out_size)
{
    const float* X    = (const float*)d_in[0];
    const float* mask = (const float*)d_in[1];
    const float* Wq   = (const float*)d_in[2];
    const float* bq   = (const float*)d_in[3];
    const float* Wk   = (const float*)d_in[4];
    const float* bk   = (const float*)d_in[5];
    const float* Wv   = (const float*)d_in[6];
    const float* bv   = (const float*)d_in[7];
    float* out = (float*)d_out;

    uint32_t *dQ, *dK, *dV;
    cudaGetSymbolAddress((void**)&dQ, g_Qh);
    cudaGetSymbolAddress((void**)&dK, g_Kh);
    cudaGetSymbolAddress((void**)&dV, g_Vp);

    cudaFuncSetAttribute(qkv_gemm3, cudaFuncAttributeMaxDynamicSharedMemorySize, GEMM_SMEM);
    const int attn_smem = ATTN_WORDS * 4;   // 55808 B
    cudaFuncSetAttribute(attn_f16, cudaFuncAttributeMaxDynamicSharedMemorySize, attn_smem);

    dim3 ggrid(HID / 128, M_ / 128, 3);   // (8, 64, 3)
    qkv_gemm3<<<ggrid, 256, GEMM_SMEM>>>(X, Wq, Wk, Wv, bq, bk, bv, dQ, dK, dV);

    dim3 agrid(S_ / 128, H_, B_);         // (16, 16, 4)
    attn_f16<<<agrid, 128, attn_smem>>>(dQ, dK, dV, mask, out);
}

// round 15
// speedup vs baseline: 1.1732x; 1.0523x over previous
#include <cuda_runtime.h>
#include <cuda_bf16.h>
#include <cstdint>

#define B_   4
#define S_   2048
#define H_   16
#define D_   64
#define HID  1024
#define M_   (B_ * S_)

#define LOG2E 1.4426950408889634f

// Pre-packed fp16 inputs for the GEMM:
//   g_Xh : X as f16x2 k-pairs, natural row-major  [M_, HID/2] u32
//   g_Wp : W as f16x2 k-pair rows Wp[kp][n]       [HID/2, HID] u32  (x3)
__device__ uint32_t g_Xh[M_ * (HID / 2)];
__device__ uint32_t g_Wpq[(HID / 2) * HID];
__device__ uint32_t g_Wpk[(HID / 2) * HID];
__device__ uint32_t g_Wpv[(HID / 2) * HID];

// GEMM outputs (attention inputs), all pre-packed fp16:
__device__ uint32_t g_Qh[B_ * H_ * S_ * 32];
__device__ uint32_t g_Kh[B_ * H_ * S_ * 32];
__device__ uint32_t g_Vp[B_ * H_ * (S_ / 2) * 64];

__device__ __forceinline__ uint32_t pack_f16x2(float lo, float hi) {
    uint32_t r;
    asm("cvt.rn.f16x2.f32 %0, %1, %2;" : "=r"(r) : "f"(hi), "f"(lo));
    return r;
}
__device__ __forceinline__ float ex2(float x) {
    float r;
    asm("ex2.approx.f32 %0, %1;" : "=f"(r) : "f"(x));
    return r;
}
__device__ __forceinline__ uint32_t smem_u32(const void* p) {
    uint32_t a;
    asm("{ .reg .u64 t; cvta.to.shared.u64 t, %1; cvt.u32.u64 %0, t; }" : "=r"(a) : "l"(p));
    return a;
}
__device__ __forceinline__ void cp16(uint32_t saddr, const void* gptr) {
    asm volatile("cp.async.ca.shared.global [%0], [%1], 16;" :: "r"(saddr), "l"(gptr));
}
#define CP_COMMIT() asm volatile("cp.async.commit_group;" ::: "memory")
#define CP_WAIT0()  asm volatile("cp.async.wait_group 0;" ::: "memory")

#define MMA_F16(c, a, b)                                               \
    asm volatile(                                                      \
        "mma.sync.aligned.m16n8k16.row.col.f32.f16.f16.f32 "           \
        "{%0,%1,%2,%3}, {%4,%5,%6,%7}, {%8,%9}, {%0,%1,%2,%3};\n"      \
        : "+f"((c)[0]), "+f"((c)[1]), "+f"((c)[2]), "+f"((c)[3])       \
        : "r"((a)[0]), "r"((a)[1]), "r"((a)[2]), "r"((a)[3]),          \
          "r"((b)[0]), "r"((b)[1]))

// ---------------------------------------------------------------------------
// Kernel 0: pack X and W into fp16 mma layouts (one-time, ~33MB of traffic).
// z=0: X contiguous f32 pairs -> u32. z=1..3: W k-pair packing.
// ---------------------------------------------------------------------------
__global__ __launch_bounds__(256) void pack_inputs(const float* __restrict__ X,
                                                   const float* __restrict__ Wq,
                                                   const float* __restrict__ Wk,
                                                   const float* __restrict__ Wv,
                                                   uint32_t* __restrict__ Xh,
                                                   uint32_t* __restrict__ Wpq,
                                                   uint32_t* __restrict__ Wpk,
                                                   uint32_t* __restrict__ Wpv)
{
    const int z = blockIdx.y;
    if (z == 0) {
        // X: M_*HID floats -> M_*HID/2 u32; process uint4 (8 floats) per iter
        const size_t n = (size_t)M_ * HID / 8;
        for (size_t i = blockIdx.x * blockDim.x + threadIdx.x; i < n;
             i += (size_t)gridDim.x * blockDim.x) {
            float4 a = reinterpret_cast<const float4*>(X)[2 * i];
            float4 b = reinterpret_cast<const float4*>(X)[2 * i + 1];
            uint4 u = {pack_f16x2(a.x, a.y), pack_f16x2(a.z, a.w),
                       pack_f16x2(b.x, b.y), pack_f16x2(b.z, b.w)};
            reinterpret_cast<uint4*>(Xh)[i] = u;
        }
    } else {
        const float* W = (z == 1) ? Wq : (z == 2) ? Wk : Wv;
        uint32_t* Wp   = (z == 1) ? Wpq : (z == 2) ? Wpk : Wpv;
        // output: (HID/2) rows x HID u32; 4 u32 per iter
        const size_t n = (size_t)(HID / 2) * HID / 4;
        for (size_t i = blockIdx.x * blockDim.x + threadIdx.x; i < n;
             i += (size_t)gridDim.x * blockDim.x) {
            size_t kp = i / (HID / 4);
            size_t n4 = (i % (HID / 4)) * 4;
            float4 r0 = *reinterpret_cast<const float4*>(&W[(2 * kp)     * HID + n4]);
            float4 r1 = *reinterpret_cast<const float4*>(&W[(2 * kp + 1) * HID + n4]);
            uint4 u = {pack_f16x2(r0.x, r1.x), pack_f16x2(r0.y, r1.y),
                       pack_f16x2(r0.z, r1.z), pack_f16x2(r0.w, r1.w)};
            *reinterpret_cast<uint4*>(&Wp[kp * HID + n4]) = u;
        }
    }
}

// ---------------------------------------------------------------------------
// Kernel A: fused QKV GEMM, fp16 operands arrive pre-packed -> pure cp.async
// staging, double-buffered, no register staging / no convert phase.
// 128x128 block, BK=32 (16 kpairs/chunk), 256 threads, warp tile 64x32.
// ---------------------------------------------------------------------------
#define AH_S 20    // A: [128 rows][16 kpair u32] + 4 pad
#define BP_S 136   // B: [16 kpairs][128 n u32] + 8 pad
#define AH_W (128 * AH_S)
#define BP_W (16 * BP_S)
#define STG_W (AH_W + BP_W)
#define GEMM_SMEM (2 * STG_W * 4)    // 37888 B

__global__ __launch_bounds__(256, 2) void qkv_gemm3(const uint32_t* __restrict__ Xh,
                                                    const uint32_t* __restrict__ Wpq,
                                                    const uint32_t* __restrict__ Wpk,
                                                    const uint32_t* __restrict__ Wpv,
                                                    const float* __restrict__ bq,
                                                    const float* __restrict__ bk,
                                                    const float* __restrict__ bv,
                                                    uint32_t* __restrict__ oQ,
                                                    uint32_t* __restrict__ oK,
                                                    uint32_t* __restrict__ oVp)
{
    extern __shared__ uint32_t smg[];
    const uint32_t sbase = smem_u32(smg);

    const int z = blockIdx.z;
    const uint32_t* Wp = (z == 0) ? Wpq : (z == 1) ? Wpk : Wpv;
    const float* bias  = (z == 0) ? bq : (z == 1) ? bk : bv;

    const int tid  = threadIdx.x;
    const int warp = tid >> 5;
    const int lane = tid & 31;
    const int grp  = lane >> 2;
    const int thr  = lane & 3;
    const int wm   = warp >> 2;
    const int wn   = warp & 3;
    const int m0   = blockIdx.y * 128;
    const int n0   = blockIdx.x * 128;

    // per-thread cp.async coordinates
    const int arow = tid >> 2, ac4 = (tid & 3) * 4;      // A: +64 rows per t
    const int bkp  = tid >> 5, bn4 = (tid & 31) * 4;     // B: +8 kpairs per t

    float acc[4][4][4];
    #pragma unroll
    for (int mt = 0; mt < 4; ++mt)
        #pragma unroll
        for (int nt = 0; nt < 4; ++nt)
            #pragma unroll
            for (int r = 0; r < 4; ++r) acc[mt][nt][r] = 0.f;

    // prologue: issue chunk 0
    #pragma unroll
    for (int t = 0; t < 2; ++t) {
        int row = arow + t * 64;
        cp16(sbase + (row * AH_S + ac4) * 4, &Xh[(size_t)(m0 + row) * (HID / 2) + ac4]);
        int kp = bkp + t * 8;
        cp16(sbase + (AH_W + kp * BP_S + bn4) * 4, &Wp[(size_t)kp * HID + n0 + bn4]);
    }
    CP_COMMIT();

    for (int i = 0; i < 32; ++i) {
        const int bu = i & 1;
        const uint32_t* Ah = smg + bu * STG_W;
        const uint32_t* Bp = Ah + AH_W;

        CP_WAIT0();
        __syncthreads();   // chunk i staged; compute(i-1) done -> other buffer free

        if (i + 1 < 32) {
            const int kp0 = (i + 1) * 16;
            const uint32_t off = (bu ^ 1) * STG_W;
            #pragma unroll
            for (int t = 0; t < 2; ++t) {
                int row = arow + t * 64;
                cp16(sbase + (off + row * AH_S + ac4) * 4,
                     &Xh[(size_t)(m0 + row) * (HID / 2) + kp0 + ac4]);
                int kp = bkp + t * 8;
                cp16(sbase + (off + AH_W + kp * BP_S + bn4) * 4,
                     &Wp[(size_t)(kp0 + kp) * HID + n0 + bn4]);
            }
            CP_COMMIT();
        }

        #pragma unroll
        for (int s = 0; s < 2; ++s) {
            uint32_t a[4][4], b[4][2];
            #pragma unroll
            for (int mt = 0; mt < 4; ++mt) {
                int r = wm * 64 + mt * 16 + grp;
                a[mt][0] = Ah[r * AH_S + s * 8 + thr];
                a[mt][1] = Ah[(r + 8) * AH_S + s * 8 + thr];
                a[mt][2] = Ah[r * AH_S + s * 8 + 4 + thr];
                a[mt][3] = Ah[(r + 8) * AH_S + s * 8 + 4 + thr];
            }
            #pragma unroll
            for (int nt = 0; nt < 4; ++nt) {
                int c = wn * 32 + nt * 8 + grp;
                b[nt][0] = Bp[(s * 8 + thr)     * BP_S + c];
                b[nt][1] = Bp[(s * 8 + thr + 4) * BP_S + c];
            }
            #pragma unroll
            for (int mt = 0; mt < 4; ++mt)
                #pragma unroll
                for (int nt = 0; nt < 4; ++nt)
                    MMA_F16(acc[mt][nt], a[mt], b[nt]);
        }
    }

    // Epilogue: bias + pack + scatter (unchanged from R14)
    const float qsc = 0.125f * LOG2E;
    #pragma unroll
    for (int mt = 0; mt < 4; ++mt) {
        #pragma unroll
        for (int nt = 0; nt < 4; ++nt) {
            #pragma unroll
            for (int half = 0; half < 2; ++half) {
                int m = m0 + wm * 64 + mt * 16 + grp + half * 8;
                int bb = m >> 11, s = m & 2047;
                int n = n0 + wn * 32 + nt * 8 + 2 * thr;
                int h = n >> 6, d = n & 63;
                float vx = acc[mt][nt][half * 2 + 0] + bias[n];
                float vy = acc[mt][nt][half * 2 + 1] + bias[n + 1];
                size_t rowbase = ((size_t)(bb * H_ + h) * S_) + s;
                if (z == 2) {
                    float px = __shfl_xor_sync(0xffffffffu, vx, 4);
                    float py = __shfl_xor_sync(0xffffffffu, vy, 4);
                    if ((grp & 1) == 0) {
                        uint2 u = {pack_f16x2(vx, px), pack_f16x2(vy, py)};
                        *reinterpret_cast<uint2*>(
                            &oVp[(((size_t)(bb * H_ + h) * (S_ / 2)) + (s >> 1)) * 64 + d]) = u;
                    }
                } else if (z == 0) {
                    oQ[rowbase * 32 + (d >> 1)] = pack_f16x2(vx * qsc, vy * qsc);
                } else {
                    oK[rowbase * 32 + (d >> 1)] = pack_f16x2(vx, vy);
                }
            }
        }
    }
}

// ---------------------------------------------------------------------------
// Kernel B: flash attention (unchanged from R14).
// ---------------------------------------------------------------------------
#define QH 36
#define KP 36
#define VP 72
#define QW2     (128 * QH)
#define OFF_KP0 QW2
#define OFF_KP1 (QW2 + 64 * KP)
#define OFF_V0  (OFF_KP1 + 64 * KP)
#define OFF_V1  (OFF_V0 + 32 * VP)
#define OFF_M0  (OFF_V1 + 32 * VP)
#define OFF_M1  (OFF_M0 + 64)
#define ATTN_WORDS (OFF_M1 + 64)

__global__ __launch_bounds__(128) void attn_f16(const uint32_t* __restrict__ Qh,
                                                const uint32_t* __restrict__ Kh,
                                                const uint32_t* __restrict__ Vp,
                                                const float* __restrict__ mask,
                                                float* __restrict__ out)
{
    extern __shared__ uint32_t sm[];
    const uint32_t sbase = smem_u32(sm);

    const int tid  = threadIdx.x;
    const int warp = tid >> 5;
    const int lane = tid & 31;
    const int grp  = lane >> 2;
    const int thr  = lane & 3;
    const int q0   = blockIdx.x * 128;
    const int h    = blockIdx.y;
    const int b    = blockIdx.z;
    const size_t pbase = (size_t)(b * H_ + h) * S_ * 32;
    const size_t vpb   = (size_t)(b * H_ + h) * (S_ / 2) * 64;
    const int wr0 = warp * 32;

    #pragma unroll
    for (int t = 0; t < 8; ++t) {
        int i = tid + t * 128;
        int r = i >> 3, c4 = (i & 7) * 4;
        cp16(sbase + (r * QH + c4) * 4, &Qh[pbase + (size_t)(q0 + r) * 32 + c4]);
    }
    #pragma unroll
    for (int t = 0; t < 4; ++t) {
        int i = tid + t * 128;
        int r = i >> 3, c4 = (i & 7) * 4;
        cp16(sbase + (OFF_KP0 + r * KP + c4) * 4, &Kh[pbase + (size_t)r * 32 + c4]);
    }
    #pragma unroll
    for (int t = 0; t < 4; ++t) {
        int i = tid + t * 128;
        int r2 = i >> 4, c4 = (i & 15) * 4;
        cp16(sbase + (OFF_V0 + r2 * VP + c4) * 4, &Vp[vpb + (size_t)r2 * 64 + c4]);
    }
    if (tid < 16) cp16(sbase + (OFF_M0 + tid * 4) * 4, &mask[b * S_ + tid * 4]);
    CP_COMMIT();

    float mrun[4] = {-1e30f, -1e30f, -1e30f, -1e30f};
    float lrun[4] = {0.f, 0.f, 0.f, 0.f};
    float o[2][8][4];
    #pragma unroll
    for (int at = 0; at < 2; ++at)
        #pragma unroll
        for (int nt = 0; nt < 8; ++nt)
            #pragma unroll
            for (int r = 0; r < 4; ++r) o[at][nt][r] = 0.f;

    for (int it = 0; it < 32; ++it) {
        const int bu = it & 1;
        const uint32_t kpo = bu ? OFF_KP1 : OFF_KP0;
        const uint32_t vpo = bu ? OFF_V1  : OFF_V0;
        const float* msk = (const float*)(sm + (bu ? OFF_M1 : OFF_M0));

        CP_WAIT0();
        __syncthreads();

        if (it + 1 < 32) {
            const int kn = (it + 1) * 64;
            const uint32_t kdo = bu ? OFF_KP0 : OFF_KP1;
            const uint32_t vdo = bu ? OFF_V0  : OFF_V1;
            #pragma unroll
            for (int t = 0; t < 4; ++t) {
                int i = tid + t * 128;
                int r = i >> 3, c4 = (i & 7) * 4;
                cp16(sbase + (kdo + r * KP + c4) * 4,
                     &Kh[pbase + (size_t)(kn + r) * 32 + c4]);
            }
            #pragma unroll
            for (int t = 0; t < 4; ++t) {
                int i = tid + t * 128;
                int r2 = i >> 4, c4 = (i & 15) * 4;
                cp16(sbase + (vdo + r2 * VP + c4) * 4,
                     &Vp[vpb + (size_t)((it + 1) * 32 + r2) * 64 + c4]);
            }
            if (tid < 16)
                cp16(sbase + ((bu ? OFF_M0 : OFF_M1) + tid * 4) * 4,
                     &mask[b * S_ + kn + tid * 4]);
            CP_COMMIT();
        }

        float s[2][8][4];
        #pragma unroll
        for (int at = 0; at < 2; ++at)
            #pragma unroll
            for (int nt = 0; nt < 8; ++nt)
                #pragma unroll
                for (int r = 0; r < 4; ++r) s[at][nt][r] = 0.f;

        #pragma unroll
        for (int ks = 0; ks < 4; ++ks) {
            uint32_t bfr[8][2];
            #pragma unroll
            for (int nt = 0; nt < 8; ++nt) {
                int key = nt * 8 + grp;
                bfr[nt][0] = sm[kpo + key * KP + ks * 8 + thr];
                bfr[nt][1] = sm[kpo + key * KP + ks * 8 + 4 + thr];
            }
            #pragma unroll
            for (int at = 0; at < 2; ++at) {
                int r0 = wr0 + at * 16 + grp;
                uint32_t a[4];
                a[0] = sm[r0 * QH + ks * 8 + thr];
                a[1] = sm[(r0 + 8) * QH + ks * 8 + thr];
                a[2] = sm[r0 * QH + ks * 8 + 4 + thr];
                a[3] = sm[(r0 + 8) * QH + ks * 8 + 4 + thr];
                #pragma unroll
                for (int nt = 0; nt < 8; ++nt)
                    MMA_F16(s[at][nt], a, bfr[nt]);
            }
        }

        uint32_t pb[2][8][2];
        #pragma unroll
        for (int at = 0; at < 2; ++at) {
            float rmax0 = -1e30f, rmax1 = -1e30f;
            #pragma unroll
            for (int nt = 0; nt < 8; ++nt) {
                int c0 = nt * 8 + 2 * thr;
                float mk0 = msk[c0], mk1 = msk[c0 + 1];
                s[at][nt][0] = fmaf(mk0, LOG2E, s[at][nt][0]);
                s[at][nt][1] = fmaf(mk1, LOG2E, s[at][nt][1]);
                s[at][nt][2] = fmaf(mk0, LOG2E, s[at][nt][2]);
                s[at][nt][3] = fmaf(mk1, LOG2E, s[at][nt][3]);
                rmax0 = fmaxf(rmax0, fmaxf(s[at][nt][0], s[at][nt][1]));
                rmax1 = fmaxf(rmax1, fmaxf(s[at][nt][2], s[at][nt][3]));
            }
            rmax0 = fmaxf(rmax0, __shfl_xor_sync(0xffffffffu, rmax0, 1));
            rmax0 = fmaxf(rmax0, __shfl_xor_sync(0xffffffffu, rmax0, 2));
            rmax1 = fmaxf(rmax1, __shfl_xor_sync(0xffffffffu, rmax1, 1));
            rmax1 = fmaxf(rmax1, __shfl_xor_sync(0xffffffffu, rmax1, 2));

            const int g0 = at * 2, g1 = at * 2 + 1;
            const float mnew0 = fmaxf(mrun[g0], rmax0);
            const float mnew1 = fmaxf(mrun[g1], rmax1);
            float sum0 = 0.f, sum1 = 0.f;
            #pragma unroll
            for (int nt = 0; nt < 8; ++nt) {
                s[at][nt][0] = ex2(s[at][nt][0] - mnew0);
                s[at][nt][1] = ex2(s[at][nt][1] - mnew0);
                s[at][nt][2] = ex2(s[at][nt][2] - mnew1);
                s[at][nt][3] = ex2(s[at][nt][3] - mnew1);
                sum0 += s[at][nt][0] + s[at][nt][1];
                sum1 += s[at][nt][2] + s[at][nt][3];
                pb[at][nt][0] = pack_f16x2(s[at][nt][0], s[at][nt][1]);
                pb[at][nt][1] = pack_f16x2(s[at][nt][2], s[at][nt][3]);
            }
            sum0 += __shfl_xor_sync(0xffffffffu, sum0, 1);
            sum0 += __shfl_xor_sync(0xffffffffu, sum0, 2);
            sum1 += __shfl_xor_sync(0xffffffffu, sum1, 1);
            sum1 += __shfl_xor_sync(0xffffffffu, sum1, 2);

            const float cf0 = ex2(mrun[g0] - mnew0);
            const float cf1 = ex2(mrun[g1] - mnew1);
            mrun[g0] = mnew0;  lrun[g0] = lrun[g0] * cf0 + sum0;
            mrun[g1] = mnew1;  lrun[g1] = lrun[g1] * cf1 + sum1;

            #pragma unroll
            for (int nt = 0; nt < 8; ++nt) {
                o[at][nt][0] *= cf0;  o[at][nt][1] *= cf0;
                o[at][nt][2] *= cf1;  o[at][nt][3] *= cf1;
            }
        }

        #pragma unroll
        for (int sstep = 0; sstep < 4; ++sstep) {
            uint32_t bfr[8][2];
            #pragma unroll
            for (int nt = 0; nt < 8; ++nt) {
                int d = nt * 8 + grp;
                bfr[nt][0] = sm[vpo + (sstep * 8 + thr)     * VP + d];
                bfr[nt][1] = sm[vpo + (sstep * 8 + thr + 4) * VP + d];
            }
            #pragma unroll
            for (int at = 0; at < 2; ++at) {
                uint32_t a[4] = {pb[at][2 * sstep][0], pb[at][2 * sstep][1],
                                 pb[at][2 * sstep + 1][0], pb[at][2 * sstep + 1][1]};
                #pragma unroll
                for (int nt = 0; nt < 8; ++nt)
                    MMA_F16(o[at][nt], a, bfr[nt]);
            }
        }
    }

    #pragma unroll
    for (int at = 0; at < 2; ++at) {
        #pragma unroll
        for (int half = 0; half < 2; ++half) {
            const int g = at * 2 + half;
            const float inv = 1.f / lrun[g];
            const int q = q0 + wr0 + at * 16 + grp + half * 8;
            #pragma unroll
            for (int nt = 0; nt < 8; ++nt) {
                int d = nt * 8 + 2 * thr;
                float2 v = {o[at][nt][half * 2 + 0] * inv,
                            o[at][nt][half * 2 + 1] * inv};
                *reinterpret_cast<float2*>(
                    &out[((size_t)(b * S_ + q)) * HID + h * D_ + d]) = v;
            }
        }
    }
}

// ---------------------------------------------------------------------------
// Launch
// ---------------------------------------------------------------------------
extern "C" void kernel_launch(void* const* d_in, const int* in_sizes, int n_in,
                              void* d_out, int out_size)
{
    const float* X    = (const float*)d_in[0];
    const float* mask = (const float*)d_in[1];
    const float* Wq   = (const float*)d_in[2];
    const float* bq   = (const float*)d_in[3];
    const float* Wk   = (const float*)d_in[4];
    const float* bk   = (const float*)d_in[5];
    const float* Wv   = (const float*)d_in[6];
    const float* bv   = (const float*)d_in[7];
    float* out = (float*)d_out;

    uint32_t *dXh, *dWpq, *dWpk, *dWpv, *dQ, *dK, *dV;
    cudaGetSymbolAddress((void**)&dXh,  g_Xh);
    cudaGetSymbolAddress((void**)&dWpq, g_Wpq);
    cudaGetSymbolAddress((void**)&dWpk, g_Wpk);
    cudaGetSymbolAddress((void**)&dWpv, g_Wpv);
    cudaGetSymbolAddress((void**)&dQ,   g_Qh);
    cudaGetSymbolAddress((void**)&dK,   g_Kh);
    cudaGetSymbolAddress((void**)&dV,   g_Vp);

    cudaFuncSetAttribute(qkv_gemm3, cudaFuncAttributeMaxDynamicSharedMemorySize, GEMM_SMEM);
    const int attn_smem = ATTN_WORDS * 4;
    cudaFuncSetAttribute(attn_f16, cudaFuncAttributeMaxDynamicSharedMemorySize, attn_smem);

    dim3 pgrid(512, 4);
    pack_inputs<<<pgrid, 256>>>(X, Wq, Wk, Wv, dXh, dWpq, dWpk, dWpv);

    dim3 ggrid(HID / 128, M_ / 128, 3);   // (8, 64, 3)
    qkv_gemm3<<<ggrid, 256, GEMM_SMEM>>>(dXh, dWpq, dWpk, dWpv, bq, bk, bv, dQ, dK, dV);

    dim3 agrid(S_ / 128, H_, B_);         // (16, 16, 4)
    attn_f16<<<agrid, 128, attn_smem>>>(dQ, dK, dV, mask, out);
}

// round 16
// speedup vs baseline: 1.2518x; 1.0671x over previous
#include <cuda_runtime.h>
#include <cuda_bf16.h>
#include <cstdint>

#define B_   4
#define S_   2048
#define H_   16
#define D_   64
#define HID  1024
#define M_   (B_ * S_)

#define LOG2E 1.4426950408889634f

__device__ uint32_t g_Xh[M_ * (HID / 2)];
__device__ uint32_t g_Wpq[(HID / 2) * HID];
__device__ uint32_t g_Wpk[(HID / 2) * HID];
__device__ uint32_t g_Wpv[(HID / 2) * HID];

__device__ uint32_t g_Qh[B_ * H_ * S_ * 32];
__device__ uint32_t g_Kh[B_ * H_ * S_ * 32];
__device__ uint32_t g_Vp[B_ * H_ * (S_ / 2) * 64];

__device__ __forceinline__ uint32_t pack_f16x2(float lo, float hi) {
    uint32_t r;
    asm("cvt.rn.f16x2.f32 %0, %1, %2;" : "=r"(r) : "f"(hi), "f"(lo));
    return r;
}
__device__ __forceinline__ float ex2(float x) {
    float r;
    asm("ex2.approx.f32 %0, %1;" : "=f"(r) : "f"(x));
    return r;
}
__device__ __forceinline__ uint32_t smem_u32(const void* p) {
    uint32_t a;
    asm("{ .reg .u64 t; cvta.to.shared.u64 t, %1; cvt.u32.u64 %0, t; }" : "=r"(a) : "l"(p));
    return a;
}
__device__ __forceinline__ void cp16(uint32_t saddr, const void* gptr) {
    asm volatile("cp.async.ca.shared.global [%0], [%1], 16;" :: "r"(saddr), "l"(gptr));
}
#define CP_COMMIT() asm volatile("cp.async.commit_group;" ::: "memory")
#define CP_WAIT0()  asm volatile("cp.async.wait_group 0;" ::: "memory")

#define MMA_F16(c, a, b)                                               \
    asm volatile(                                                      \
        "mma.sync.aligned.m16n8k16.row.col.f32.f16.f16.f32 "           \
        "{%0,%1,%2,%3}, {%4,%5,%6,%7}, {%8,%9}, {%0,%1,%2,%3};\n"      \
        : "+f"((c)[0]), "+f"((c)[1]), "+f"((c)[2]), "+f"((c)[3])       \
        : "r"((a)[0]), "r"((a)[1]), "r"((a)[2]), "r"((a)[3]),          \
          "r"((b)[0]), "r"((b)[1]))

#define LDM_X4(r0, r1, r2, r3, addr)                                   \
    asm volatile("ldmatrix.sync.aligned.m8n8.x4.shared.b16 "           \
                 "{%0,%1,%2,%3}, [%4];"                                \
                 : "=r"(r0), "=r"(r1), "=r"(r2), "=r"(r3) : "r"(addr))

// ---------------------------------------------------------------------------
// Kernel 0: pack X and W into fp16 mma layouts (unchanged from R15).
// ---------------------------------------------------------------------------
__global__ __launch_bounds__(256) void pack_inputs(const float* __restrict__ X,
                                                   const float* __restrict__ Wq,
                                                   const float* __restrict__ Wk,
                                                   const float* __restrict__ Wv,
                                                   uint32_t* __restrict__ Xh,
                                                   uint32_t* __restrict__ Wpq,
                                                   uint32_t* __restrict__ Wpk,
                                                   uint32_t* __restrict__ Wpv)
{
    const int z = blockIdx.y;
    if (z == 0) {
        const size_t n = (size_t)M_ * HID / 8;
        for (size_t i = blockIdx.x * blockDim.x + threadIdx.x; i < n;
             i += (size_t)gridDim.x * blockDim.x) {
            float4 a = reinterpret_cast<const float4*>(X)[2 * i];
            float4 b = reinterpret_cast<const float4*>(X)[2 * i + 1];
            uint4 u = {pack_f16x2(a.x, a.y), pack_f16x2(a.z, a.w),
                       pack_f16x2(b.x, b.y), pack_f16x2(b.z, b.w)};
            reinterpret_cast<uint4*>(Xh)[i] = u;
        }
    } else {
        const float* W = (z == 1) ? Wq : (z == 2) ? Wk : Wv;
        uint32_t* Wp   = (z == 1) ? Wpq : (z == 2) ? Wpk : Wpv;
        const size_t n = (size_t)(HID / 2) * HID / 4;
        for (size_t i = blockIdx.x * blockDim.x + threadIdx.x; i < n;
             i += (size_t)gridDim.x * blockDim.x) {
            size_t kp = i / (HID / 4);
            size_t n4 = (i % (HID / 4)) * 4;
            float4 r0 = *reinterpret_cast<const float4*>(&W[(2 * kp)     * HID + n4]);
            float4 r1 = *reinterpret_cast<const float4*>(&W[(2 * kp + 1) * HID + n4]);
            uint4 u = {pack_f16x2(r0.x, r1.x), pack_f16x2(r0.y, r1.y),
                       pack_f16x2(r0.z, r1.z), pack_f16x2(r0.w, r1.w)};
            *reinterpret_cast<uint4*>(&Wp[kp * HID + n4]) = u;
        }
    }
}

// ---------------------------------------------------------------------------
// Kernel A: fused QKV GEMM. BK=64 (4 k16 steps / barrier), pure cp.async
// staging, ldmatrix A-fragments. 128x128 block, 256 threads, warp 64x32.
// ---------------------------------------------------------------------------
#define AH_S 36    // A: [128 rows][32 kpair u32] + 4 pad  (stride%32 = 4)
#define BP_S 136   // B: [32 kpairs][128 n u32] + 8 pad
#define AH_W (128 * AH_S)            // 4608
#define BP_W (32 * BP_S)             // 4352
#define STG_W (AH_W + BP_W)          // 8960
#define GEMM_SMEM (2 * STG_W * 4)    // 71680 B

__global__ __launch_bounds__(256, 2) void qkv_gemm3(const uint32_t* __restrict__ Xh,
                                                    const uint32_t* __restrict__ Wpq,
                                                    const uint32_t* __restrict__ Wpk,
                                                    const uint32_t* __restrict__ Wpv,
                                                    const float* __restrict__ bq,
                                                    const float* __restrict__ bk,
                                                    const float* __restrict__ bv,
                                                    uint32_t* __restrict__ oQ,
                                                    uint32_t* __restrict__ oK,
                                                    uint32_t* __restrict__ oVp)
{
    extern __shared__ uint32_t smg[];
    const uint32_t sbase = smem_u32(smg);

    const int z = blockIdx.z;
    const uint32_t* Wp = (z == 0) ? Wpq : (z == 1) ? Wpk : Wpv;
    const float* bias  = (z == 0) ? bq : (z == 1) ? bk : bv;

    const int tid  = threadIdx.x;
    const int warp = tid >> 5;
    const int lane = tid & 31;
    const int grp  = lane >> 2;
    const int thr  = lane & 3;
    const int wm   = warp >> 2;
    const int wn   = warp & 3;
    const int m0   = blockIdx.y * 128;
    const int n0   = blockIdx.x * 128;

    // ldmatrix lane coords for A (x4: m0/m8 x k-lo/k-hi)
    const int a_r = (lane & 7) + ((lane >> 3) & 1) * 8;
    const int a_c = (lane >> 4) * 4;
    const uint32_t a_lm = sbase + (((wm * 64 + a_r) * AH_S) + a_c) * 4;

    float acc[4][4][4];
    #pragma unroll
    for (int mt = 0; mt < 4; ++mt)
        #pragma unroll
        for (int nt = 0; nt < 4; ++nt)
            #pragma unroll
            for (int r = 0; r < 4; ++r) acc[mt][nt][r] = 0.f;

    // prologue: issue chunk 0 (A: 1024 16B chunks, B: 1024 -> 4+4 per thread)
    #pragma unroll
    for (int t = 0; t < 4; ++t) {
        int i = tid + t * 256;
        int row = i >> 3, c4 = (i & 7) * 4;
        cp16(sbase + (row * AH_S + c4) * 4, &Xh[(size_t)(m0 + row) * (HID / 2) + c4]);
        int kp = i >> 5, n4 = (i & 31) * 4;
        cp16(sbase + (AH_W + kp * BP_S + n4) * 4, &Wp[(size_t)kp * HID + n0 + n4]);
    }
    CP_COMMIT();

    for (int i = 0; i < 16; ++i) {
        const int bu = i & 1;
        const uint32_t* Bp = smg + bu * STG_W + AH_W;
        const uint32_t abuf = a_lm + bu * (STG_W * 4);

        CP_WAIT0();
        __syncthreads();

        if (i + 1 < 16) {
            const int kp0 = (i + 1) * 32;
            const uint32_t off = (bu ^ 1) * STG_W;
            #pragma unroll
            for (int t = 0; t < 4; ++t) {
                int ii = tid + t * 256;
                int row = ii >> 3, c4 = (ii & 7) * 4;
                cp16(sbase + (off + row * AH_S + c4) * 4,
                     &Xh[(size_t)(m0 + row) * (HID / 2) + kp0 + c4]);
                int kp = ii >> 5, n4 = (ii & 31) * 4;
                cp16(sbase + (off + AH_W + kp * BP_S + n4) * 4,
                     &Wp[(size_t)(kp0 + kp) * HID + n0 + n4]);
            }
            CP_COMMIT();
        }

        #pragma unroll
        for (int s = 0; s < 4; ++s) {
            uint32_t a[4][4], b[4][2];
            #pragma unroll
            for (int mt = 0; mt < 4; ++mt)
                LDM_X4(a[mt][0], a[mt][1], a[mt][2], a[mt][3],
                       abuf + (mt * 16 * AH_S + s * 8) * 4);
            #pragma unroll
            for (int nt = 0; nt < 4; ++nt) {
                int c = wn * 32 + nt * 8 + grp;
                b[nt][0] = Bp[(s * 8 + thr)     * BP_S + c];
                b[nt][1] = Bp[(s * 8 + thr + 4) * BP_S + c];
            }
            #pragma unroll
            for (int mt = 0; mt < 4; ++mt)
                #pragma unroll
                for (int nt = 0; nt < 4; ++nt)
                    MMA_F16(acc[mt][nt], a[mt], b[nt]);
        }
    }

    // Epilogue: bias + pack + scatter (unchanged)
    const float qsc = 0.125f * LOG2E;
    #pragma unroll
    for (int mt = 0; mt < 4; ++mt) {
        #pragma unroll
        for (int nt = 0; nt < 4; ++nt) {
            #pragma unroll
            for (int half = 0; half < 2; ++half) {
                int m = m0 + wm * 64 + mt * 16 + grp + half * 8;
                int bb = m >> 11, s = m & 2047;
                int n = n0 + wn * 32 + nt * 8 + 2 * thr;
                int h = n >> 6, d = n & 63;
                float vx = acc[mt][nt][half * 2 + 0] + bias[n];
                float vy = acc[mt][nt][half * 2 + 1] + bias[n + 1];
                size_t rowbase = ((size_t)(bb * H_ + h) * S_) + s;
                if (z == 2) {
                    float px = __shfl_xor_sync(0xffffffffu, vx, 4);
                    float py = __shfl_xor_sync(0xffffffffu, vy, 4);
                    if ((grp & 1) == 0) {
                        uint2 u = {pack_f16x2(vx, px), pack_f16x2(vy, py)};
                        *reinterpret_cast<uint2*>(
                            &oVp[(((size_t)(bb * H_ + h) * (S_ / 2)) + (s >> 1)) * 64 + d]) = u;
                    }
                } else if (z == 0) {
                    oQ[rowbase * 32 + (d >> 1)] = pack_f16x2(vx * qsc, vy * qsc);
                } else {
                    oK[rowbase * 32 + (d >> 1)] = pack_f16x2(vx, vy);
                }
            }
        }
    }
}

// ---------------------------------------------------------------------------
// Kernel B: flash attention; ldmatrix for Q (A-frags) + K (B-frags).
// ---------------------------------------------------------------------------
#define QH 36
#define KP 36
#define VP 72
#define QW2     (128 * QH)
#define OFF_KP0 QW2
#define OFF_KP1 (QW2 + 64 * KP)
#define OFF_V0  (OFF_KP1 + 64 * KP)
#define OFF_V1  (OFF_V0 + 32 * VP)
#define OFF_M0  (OFF_V1 + 32 * VP)
#define OFF_M1  (OFF_M0 + 64)
#define ATTN_WORDS (OFF_M1 + 64)

__global__ __launch_bounds__(128) void attn_f16(const uint32_t* __restrict__ Qh,
                                                const uint32_t* __restrict__ Kh,
                                                const uint32_t* __restrict__ Vp,
                                                const float* __restrict__ mask,
                                                float* __restrict__ out)
{
    extern __shared__ uint32_t sm[];
    const uint32_t sbase = smem_u32(sm);

    const int tid  = threadIdx.x;
    const int warp = tid >> 5;
    const int lane = tid & 31;
    const int grp  = lane >> 2;
    const int thr  = lane & 3;
    const int q0   = blockIdx.x * 128;
    const int h    = blockIdx.y;
    const int b    = blockIdx.z;
    const size_t pbase = (size_t)(b * H_ + h) * S_ * 32;
    const size_t vpb   = (size_t)(b * H_ + h) * (S_ / 2) * 64;
    const int wr0 = warp * 32;

    // ldmatrix lane coords
    const int a_r = (lane & 7) + ((lane >> 3) & 1) * 8;   // A (Q): m-lo/hi x k-lo/hi
    const int a_c = (lane >> 4) * 4;
    const uint32_t q_lm = sbase + (((wr0 + a_r) * QH) + a_c) * 4;
    const int k_r = (lane & 7) + (lane >> 4) * 8;         // B (K): nt-pair x k-lo/hi
    const int k_c = ((lane >> 3) & 1) * 4;

    #pragma unroll
    for (int t = 0; t < 8; ++t) {
        int i = tid + t * 128;
        int r = i >> 3, c4 = (i & 7) * 4;
        cp16(sbase + (r * QH + c4) * 4, &Qh[pbase + (size_t)(q0 + r) * 32 + c4]);
    }
    #pragma unroll
    for (int t = 0; t < 4; ++t) {
        int i = tid + t * 128;
        int r = i >> 3, c4 = (i & 7) * 4;
        cp16(sbase + (OFF_KP0 + r * KP + c4) * 4, &Kh[pbase + (size_t)r * 32 + c4]);
    }
    #pragma unroll
    for (int t = 0; t < 4; ++t) {
        int i = tid + t * 128;
        int r2 = i >> 4, c4 = (i & 15) * 4;
        cp16(sbase + (OFF_V0 + r2 * VP + c4) * 4, &Vp[vpb + (size_t)r2 * 64 + c4]);
    }
    if (tid < 16) cp16(sbase + (OFF_M0 + tid * 4) * 4, &mask[b * S_ + tid * 4]);
    CP_COMMIT();

    float mrun[4] = {-1e30f, -1e30f, -1e30f, -1e30f};
    float lrun[4] = {0.f, 0.f, 0.f, 0.f};
    float o[2][8][4];
    #pragma unroll
    for (int at = 0; at < 2; ++at)
        #pragma unroll
        for (int nt = 0; nt < 8; ++nt)
            #pragma unroll
            for (int r = 0; r < 4; ++r) o[at][nt][r] = 0.f;

    for (int it = 0; it < 32; ++it) {
        const int bu = it & 1;
        const uint32_t kpo = bu ? OFF_KP1 : OFF_KP0;
        const uint32_t vpo = bu ? OFF_V1  : OFF_V0;
        const float* msk = (const float*)(sm + (bu ? OFF_M1 : OFF_M0));
        const uint32_t k_lm = sbase + kpo * 4 + (k_r * KP + k_c) * 4;

        CP_WAIT0();
        __syncthreads();

        if (it + 1 < 32) {
            const int kn = (it + 1) * 64;
            const uint32_t kdo = bu ? OFF_KP0 : OFF_KP1;
            const uint32_t vdo = bu ? OFF_V0  : OFF_V1;
            #pragma unroll
            for (int t = 0; t < 4; ++t) {
                int i = tid + t * 128;
                int r = i >> 3, c4 = (i & 7) * 4;
                cp16(sbase + (kdo + r * KP + c4) * 4,
                     &Kh[pbase + (size_t)(kn + r) * 32 + c4]);
            }
            #pragma unroll
            for (int t = 0; t < 4; ++t) {
                int i = tid + t * 128;
                int r2 = i >> 4, c4 = (i & 15) * 4;
                cp16(sbase + (vdo + r2 * VP + c4) * 4,
                     &Vp[vpb + (size_t)((it + 1) * 32 + r2) * 64 + c4]);
            }
            if (tid < 16)
                cp16(sbase + ((bu ? OFF_M0 : OFF_M1) + tid * 4) * 4,
                     &mask[b * S_ + kn + tid * 4]);
            CP_COMMIT();
        }

        // ---- S = Q @ K^T (ldmatrix fragments) ----
        float s[2][8][4];
        #pragma unroll
        for (int at = 0; at < 2; ++at)
            #pragma unroll
            for (int nt = 0; nt < 8; ++nt)
                #pragma unroll
                for (int r = 0; r < 4; ++r) s[at][nt][r] = 0.f;

        #pragma unroll
        for (int ks = 0; ks < 4; ++ks) {
            uint32_t bfr[8][2];
            #pragma unroll
            for (int ntp = 0; ntp < 4; ++ntp)
                LDM_X4(bfr[2 * ntp][0], bfr[2 * ntp][1],
                       bfr[2 * ntp + 1][0], bfr[2 * ntp + 1][1],
                       k_lm + (ntp * 16 * KP + ks * 8) * 4);
            #pragma unroll
            for (int at = 0; at < 2; ++at) {
                uint32_t a[4];
                LDM_X4(a[0], a[1], a[2], a[3],
                       q_lm + (at * 16 * QH + ks * 8) * 4);
                #pragma unroll
                for (int nt = 0; nt < 8; ++nt)
                    MMA_F16(s[at][nt], a, bfr[nt]);
            }
        }

        // ---- mask + online softmax (base-2); P -> f16x2 ----
        uint32_t pb[2][8][2];
        #pragma unroll
        for (int at = 0; at < 2; ++at) {
            float rmax0 = -1e30f, rmax1 = -1e30f;
            #pragma unroll
            for (int nt = 0; nt < 8; ++nt) {
                int c0 = nt * 8 + 2 * thr;
                float mk0 = msk[c0], mk1 = msk[c0 + 1];
                s[at][nt][0] = fmaf(mk0, LOG2E, s[at][nt][0]);
                s[at][nt][1] = fmaf(mk1, LOG2E, s[at][nt][1]);
                s[at][nt][2] = fmaf(mk0, LOG2E, s[at][nt][2]);
                s[at][nt][3] = fmaf(mk1, LOG2E, s[at][nt][3]);
                rmax0 = fmaxf(rmax0, fmaxf(s[at][nt][0], s[at][nt][1]));
                rmax1 = fmaxf(rmax1, fmaxf(s[at][nt][2], s[at][nt][3]));
            }
            rmax0 = fmaxf(rmax0, __shfl_xor_sync(0xffffffffu, rmax0, 1));
            rmax0 = fmaxf(rmax0, __shfl_xor_sync(0xffffffffu, rmax0, 2));
            rmax1 = fmaxf(rmax1, __shfl_xor_sync(0xffffffffu, rmax1, 1));
            rmax1 = fmaxf(rmax1, __shfl_xor_sync(0xffffffffu, rmax1, 2));

            const int g0 = at * 2, g1 = at * 2 + 1;
            const float mnew0 = fmaxf(mrun[g0], rmax0);
            const float mnew1 = fmaxf(mrun[g1], rmax1);
            float sum0 = 0.f, sum1 = 0.f;
            #pragma unroll
            for (int nt = 0; nt < 8; ++nt) {
                s[at][nt][0] = ex2(s[at][nt][0] - mnew0);
                s[at][nt][1] = ex2(s[at][nt][1] - mnew0);
                s[at][nt][2] = ex2(s[at][nt][2] - mnew1);
                s[at][nt][3] = ex2(s[at][nt][3] - mnew1);
                sum0 += s[at][nt][0] + s[at][nt][1];
                sum1 += s[at][nt][2] + s[at][nt][3];
                pb[at][nt][0] = pack_f16x2(s[at][nt][0], s[at][nt][1]);
                pb[at][nt][1] = pack_f16x2(s[at][nt][2], s[at][nt][3]);
            }
            sum0 += __shfl_xor_sync(0xffffffffu, sum0, 1);
            sum0 += __shfl_xor_sync(0xffffffffu, sum0, 2);
            sum1 += __shfl_xor_sync(0xffffffffu, sum1, 1);
            sum1 += __shfl_xor_sync(0xffffffffu, sum1, 2);

            const float cf0 = ex2(mrun[g0] - mnew0);
            const float cf1 = ex2(mrun[g1] - mnew1);
            mrun[g0] = mnew0;  lrun[g0] = lrun[g0] * cf0 + sum0;
            mrun[g1] = mnew1;  lrun[g1] = lrun[g1] * cf1 + sum1;

            #pragma unroll
            for (int nt = 0; nt < 8; ++nt) {
                o[at][nt][0] *= cf0;  o[at][nt][1] *= cf0;
                o[at][nt][2] *= cf1;  o[at][nt][3] *= cf1;
            }
        }

        // ---- O += P @ V (manual V loads; layout transposed vs ldmatrix) ----
        #pragma unroll
        for (int sstep = 0; sstep < 4; ++sstep) {
            uint32_t bfr[8][2];
            #pragma unroll
            for (int nt = 0; nt < 8; ++nt) {
                int d = nt * 8 + grp;
                bfr[nt][0] = sm[vpo + (sstep * 8 + thr)     * VP + d];
                bfr[nt][1] = sm[vpo + (sstep * 8 + thr + 4) * VP + d];
            }
            #pragma unroll
            for (int at = 0; at < 2; ++at) {
                uint32_t a[4] = {pb[at][2 * sstep][0], pb[at][2 * sstep][1],
                                 pb[at][2 * sstep + 1][0], pb[at][2 * sstep + 1][1]};
                #pragma unroll
                for (int nt = 0; nt < 8; ++nt)
                    MMA_F16(o[at][nt], a, bfr[nt]);
            }
        }
    }

    // Output
    #pragma unroll
    for (int at = 0; at < 2; ++at) {
        #pragma unroll
        for (int half = 0; half < 2; ++half) {
            const int g = at * 2 + half;
            const float inv = 1.f / lrun[g];
            const int q = q0 + wr0 + at * 16 + grp + half * 8;
            #pragma unroll
            for (int nt = 0; nt < 8; ++nt) {
                int d = nt * 8 + 2 * thr;
                float2 v = {o[at][nt][half * 2 + 0] * inv,
                            o[at][nt][half * 2 + 1] * inv};
                *reinterpret_cast<float2*>(
                    &out[((size_t)(b * S_ + q)) * HID + h * D_ + d]) = v;
            }
        }
    }
}

// ---------------------------------------------------------------------------
// Launch
// ---------------------------------------------------------------------------
extern "C" void kernel_launch(void* const* d_in, const int* in_sizes, int n_in,
                              void* d_out, int out_size)
{
    const float* X    = (const float*)d_in[0];
    const float* mask = (const float*)d_in[1];
    const float* Wq   = (const float*)d_in[2];
    const float* bq   = (const float*)d_in[3];
    const float* Wk   = (const float*)d_in[4];
    const float* bk   = (const float*)d_in[5];
    const float* Wv   = (const float*)d_in[6];
    const float* bv   = (const float*)d_in[7];
    float* out = (float*)d_out;

    uint32_t *dXh, *dWpq, *dWpk, *dWpv, *dQ, *dK, *dV;
    cudaGetSymbolAddress((void**)&dXh,  g_Xh);
    cudaGetSymbolAddress((void**)&dWpq, g_Wpq);
    cudaGetSymbolAddress((void**)&dWpk, g_Wpk);
    cudaGetSymbolAddress((void**)&dWpv, g_Wpv);
    cudaGetSymbolAddress((void**)&dQ,   g_Qh);
    cudaGetSymbolAddress((void**)&dK,   g_Kh);
    cudaGetSymbolAddress((void**)&dV,   g_Vp);

    cudaFuncSetAttribute(qkv_gemm3, cudaFuncAttributeMaxDynamicSharedMemorySize, GEMM_SMEM);
    const int attn_smem = ATTN_WORDS * 4;
    cudaFuncSetAttribute(attn_f16, cudaFuncAttributeMaxDynamicSharedMemorySize, attn_smem);

    dim3 pgrid(512, 4);
    pack_inputs<<<pgrid, 256>>>(X, Wq, Wk, Wv, dXh, dWpq, dWpk, dWpv);

    dim3 ggrid(HID / 128, M_ / 128, 3);   // (8, 64, 3)
    qkv_gemm3<<<ggrid, 256, GEMM_SMEM>>>(dXh, dWpq, dWpk, dWpv, bq, bk, bv, dQ, dK, dV);

    dim3 agrid(S_ / 128, H_, B_);         // (16, 16, 4)
    attn_f16<<<agrid, 128, attn_smem>>>(dQ, dK, dV, mask, out);
}

// round 17
// speedup vs baseline: 1.3248x; 1.0583x over previous
#include <cuda_runtime.h>
#include <cuda_bf16.h>
#include <cstdint>

#define B_   4
#define S_   2048
#define H_   16
#define D_   64
#define HID  1024
#define M_   (B_ * S_)

#define LOG2E 1.4426950408889634f

// All fp16-packed as u32 pairs along the contiguous axis:
//   g_Xh  [M_, HID/2]      (X rows)
//   g_Wh* [HID, HID/2]     (W rows, plain [k][n] f16)
//   g_Qh/g_Kh/g_Vh [B,H,S,32]  (d-pairs; Q pre-scaled by 0.125*log2e)
__device__ uint32_t g_Xh[M_ * (HID / 2)];
__device__ uint32_t g_Whq[HID * (HID / 2)];
__device__ uint32_t g_Whk[HID * (HID / 2)];
__device__ uint32_t g_Whv[HID * (HID / 2)];

__device__ uint32_t g_Qh[B_ * H_ * S_ * 32];
__device__ uint32_t g_Kh[B_ * H_ * S_ * 32];
__device__ uint32_t g_Vh[B_ * H_ * S_ * 32];

__device__ __forceinline__ uint32_t pack_f16x2(float lo, float hi) {
    uint32_t r;
    asm("cvt.rn.f16x2.f32 %0, %1, %2;" : "=r"(r) : "f"(hi), "f"(lo));
    return r;
}
__device__ __forceinline__ float ex2(float x) {
    float r;
    asm("ex2.approx.f32 %0, %1;" : "=f"(r) : "f"(x));
    return r;
}
__device__ __forceinline__ uint32_t smem_u32(const void* p) {
    uint32_t a;
    asm("{ .reg .u64 t; cvta.to.shared.u64 t, %1; cvt.u32.u64 %0, t; }" : "=r"(a) : "l"(p));
    return a;
}
__device__ __forceinline__ void cp16(uint32_t saddr, const void* gptr) {
    asm volatile("cp.async.ca.shared.global [%0], [%1], 16;" :: "r"(saddr), "l"(gptr));
}
#define CP_COMMIT() asm volatile("cp.async.commit_group;" ::: "memory")
#define CP_WAIT0()  asm volatile("cp.async.wait_group 0;" ::: "memory")

#define MMA_F16(c, a, b)                                               \
    asm volatile(                                                      \
        "mma.sync.aligned.m16n8k16.row.col.f32.f16.f16.f32 "           \
        "{%0,%1,%2,%3}, {%4,%5,%6,%7}, {%8,%9}, {%0,%1,%2,%3};\n"      \
        : "+f"((c)[0]), "+f"((c)[1]), "+f"((c)[2]), "+f"((c)[3])       \
        : "r"((a)[0]), "r"((a)[1]), "r"((a)[2]), "r"((a)[3]),          \
          "r"((b)[0]), "r"((b)[1]))

#define LDM_X4(r0, r1, r2, r3, addr)                                   \
    asm volatile("ldmatrix.sync.aligned.m8n8.x4.shared.b16 "           \
                 "{%0,%1,%2,%3}, [%4];"                                \
                 : "=r"(r0), "=r"(r1), "=r"(r2), "=r"(r3) : "r"(addr))

#define LDM_X4T(r0, r1, r2, r3, addr)                                  \
    asm volatile("ldmatrix.sync.aligned.m8n8.x4.trans.shared.b16 "     \
                 "{%0,%1,%2,%3}, [%4];"                                \
                 : "=r"(r0), "=r"(r1), "=r"(r2), "=r"(r3) : "r"(addr))

// ---------------------------------------------------------------------------
// Kernel 0: pack X / Wq / Wk / Wv -> contiguous f16x2 (one code path).
// ---------------------------------------------------------------------------
__global__ __launch_bounds__(256) void pack_inputs(const float* __restrict__ X,
                                                   const float* __restrict__ Wq,
                                                   const float* __restrict__ Wk,
                                                   const float* __restrict__ Wv,
                                                   uint32_t* __restrict__ Xh,
                                                   uint32_t* __restrict__ Whq,
                                                   uint32_t* __restrict__ Whk,
                                                   uint32_t* __restrict__ Whv)
{
    const int z = blockIdx.y;
    const float* src = (z == 0) ? X : (z == 1) ? Wq : (z == 2) ? Wk : Wv;
    uint32_t* dst    = (z == 0) ? Xh : (z == 1) ? Whq : (z == 2) ? Whk : Whv;
    const size_t n   = ((z == 0) ? (size_t)M_ * HID : (size_t)HID * HID) / 8;
    for (size_t i = blockIdx.x * blockDim.x + threadIdx.x; i < n;
         i += (size_t)gridDim.x * blockDim.x) {
        float4 a = reinterpret_cast<const float4*>(src)[2 * i];
        float4 b = reinterpret_cast<const float4*>(src)[2 * i + 1];
        uint4 u = {pack_f16x2(a.x, a.y), pack_f16x2(a.z, a.w),
                   pack_f16x2(b.x, b.y), pack_f16x2(b.z, b.w)};
        reinterpret_cast<uint4*>(dst)[i] = u;
    }
}

// ---------------------------------------------------------------------------
// Kernel A: fused QKV GEMM. BK=64, cp.async staging, ldmatrix A-frags,
// ldmatrix.trans B-frags from plain [k][n] f16 W tiles.
// ---------------------------------------------------------------------------
#define AH_S 36    // A: [128 rows][32 kpair u32] + 4 pad
#define BH_S 68    // B: [64 k rows][64 n-pair u32] + 4 pad
#define AH_W (128 * AH_S)            // 4608
#define BH_W (64 * BH_S)             // 4352
#define STG_W (AH_W + BH_W)          // 8960
#define GEMM_SMEM (2 * STG_W * 4)    // 71680 B

__global__ __launch_bounds__(256, 2) void qkv_gemm3(const uint32_t* __restrict__ Xh,
                                                    const uint32_t* __restrict__ Whq,
                                                    const uint32_t* __restrict__ Whk,
                                                    const uint32_t* __restrict__ Whv,
                                                    const float* __restrict__ bq,
                                                    const float* __restrict__ bk,
                                                    const float* __restrict__ bv,
                                                    uint32_t* __restrict__ oQ,
                                                    uint32_t* __restrict__ oK,
                                                    uint32_t* __restrict__ oV)
{
    extern __shared__ uint32_t smg[];
    const uint32_t sbase = smem_u32(smg);

    const int z = blockIdx.z;
    const uint32_t* Wh = (z == 0) ? Whq : (z == 1) ? Whk : Whv;
    const float* bias  = (z == 0) ? bq : (z == 1) ? bk : bv;

    const int tid  = threadIdx.x;
    const int warp = tid >> 5;
    const int lane = tid & 31;
    const int grp  = lane >> 2;
    const int thr  = lane & 3;
    const int wm   = warp >> 2;
    const int wn   = warp & 3;
    const int m0   = blockIdx.y * 128;
    const int n0   = blockIdx.x * 128;

    // ldmatrix lane coords
    const int a_r = (lane & 7) + ((lane >> 3) & 1) * 8;
    const int a_c = (lane >> 4) * 4;
    const uint32_t a_lm = (((wm * 64 + a_r) * AH_S) + a_c) * 4;
    const int m4  = lane >> 3;                     // trans: matrix id
    const int b_r = (m4 & 1) * 8 + (lane & 7);     // k row within 16
    const int b_c = wn * 16 + (m4 >> 1) * 4;       // n-pair col
    const uint32_t b_lm = (b_r * BH_S + b_c) * 4;

    float acc[4][4][4];
    #pragma unroll
    for (int mt = 0; mt < 4; ++mt)
        #pragma unroll
        for (int nt = 0; nt < 4; ++nt)
            #pragma unroll
            for (int r = 0; r < 4; ++r) acc[mt][nt][r] = 0.f;

    // prologue: stage chunk 0. A: 1024 chunks; B: 64 rows x 16 chunks = 1024.
    #pragma unroll
    for (int t = 0; t < 4; ++t) {
        int i = tid + t * 256;
        int row = i >> 3, c4 = (i & 7) * 4;
        cp16(sbase + (row * AH_S + c4) * 4, &Xh[(size_t)(m0 + row) * (HID / 2) + c4]);
        int kr = i >> 4, n4 = (i & 15) * 4;
        cp16(sbase + (AH_W + kr * BH_S + n4) * 4,
             &Wh[(size_t)kr * (HID / 2) + n0 / 2 + n4]);
    }
    CP_COMMIT();

    for (int i = 0; i < 16; ++i) {
        const int bu = i & 1;
        const uint32_t abuf = sbase + bu * (STG_W * 4) + a_lm;
        const uint32_t bbuf = sbase + (bu * STG_W + AH_W) * 4 + b_lm;

        CP_WAIT0();
        __syncthreads();

        if (i + 1 < 16) {
            const int k0 = (i + 1) * 64;
            const uint32_t off = (bu ^ 1) * STG_W;
            #pragma unroll
            for (int t = 0; t < 4; ++t) {
                int ii = tid + t * 256;
                int row = ii >> 3, c4 = (ii & 7) * 4;
                cp16(sbase + (off + row * AH_S + c4) * 4,
                     &Xh[(size_t)(m0 + row) * (HID / 2) + k0 / 2 + c4]);
                int kr = ii >> 4, n4 = (ii & 15) * 4;
                cp16(sbase + (off + AH_W + kr * BH_S + n4) * 4,
                     &Wh[(size_t)(k0 + kr) * (HID / 2) + n0 / 2 + n4]);
            }
            CP_COMMIT();
        }

        #pragma unroll
        for (int s = 0; s < 4; ++s) {
            uint32_t a[4][4], b[4][2];
            #pragma unroll
            for (int mt = 0; mt < 4; ++mt)
                LDM_X4(a[mt][0], a[mt][1], a[mt][2], a[mt][3],
                       abuf + (mt * 16 * AH_S + s * 8) * 4);
            #pragma unroll
            for (int ntp = 0; ntp < 2; ++ntp)
                LDM_X4T(b[2 * ntp][0], b[2 * ntp][1],
                        b[2 * ntp + 1][0], b[2 * ntp + 1][1],
                        bbuf + (s * 16 * BH_S + ntp * 8) * 4);
            #pragma unroll
            for (int mt = 0; mt < 4; ++mt)
                #pragma unroll
                for (int nt = 0; nt < 4; ++nt)
                    MMA_F16(acc[mt][nt], a[mt], b[nt]);
        }
    }

    // Epilogue: bias + pack + scatter (V now identical to K)
    const float qsc = 0.125f * LOG2E;
    #pragma unroll
    for (int mt = 0; mt < 4; ++mt) {
        #pragma unroll
        for (int nt = 0; nt < 4; ++nt) {
            #pragma unroll
            for (int half = 0; half < 2; ++half) {
                int m = m0 + wm * 64 + mt * 16 + grp + half * 8;
                int bb = m >> 11, s = m & 2047;
                int n = n0 + wn * 32 + nt * 8 + 2 * thr;
                int h = n >> 6, d = n & 63;
                float vx = acc[mt][nt][half * 2 + 0] + bias[n];
                float vy = acc[mt][nt][half * 2 + 1] + bias[n + 1];
                size_t rowbase = ((size_t)(bb * H_ + h) * S_) + s;
                uint32_t* dst = (z == 0) ? oQ : (z == 1) ? oK : oV;
                float sc = (z == 0) ? qsc : 1.f;
                dst[rowbase * 32 + (d >> 1)] = pack_f16x2(vx * sc, vy * sc);
            }
        }
    }
}

// ---------------------------------------------------------------------------
// Kernel B: flash attention; ldmatrix Q/K, ldmatrix.trans V.
// ---------------------------------------------------------------------------
#define QH 36
#define KP 36
#define VH 36
#define QW2     (128 * QH)
#define OFF_KP0 QW2
#define OFF_KP1 (QW2 + 64 * KP)
#define OFF_V0  (OFF_KP1 + 64 * KP)
#define OFF_V1  (OFF_V0 + 64 * VH)
#define OFF_M0  (OFF_V1 + 64 * VH)
#define OFF_M1  (OFF_M0 + 64)
#define ATTN_WORDS (OFF_M1 + 64)

__global__ __launch_bounds__(128) void attn_f16(const uint32_t* __restrict__ Qh,
                                                const uint32_t* __restrict__ Kh,
                                                const uint32_t* __restrict__ Vh,
                                                const float* __restrict__ mask,
                                                float* __restrict__ out)
{
    extern __shared__ uint32_t sm[];
    const uint32_t sbase = smem_u32(sm);

    const int tid  = threadIdx.x;
    const int warp = tid >> 5;
    const int lane = tid & 31;
    const int grp  = lane >> 2;
    const int thr  = lane & 3;
    const int q0   = blockIdx.x * 128;
    const int h    = blockIdx.y;
    const int b    = blockIdx.z;
    const size_t pbase = (size_t)(b * H_ + h) * S_ * 32;
    const int wr0 = warp * 32;

    // ldmatrix lane coords
    const int a_r = (lane & 7) + ((lane >> 3) & 1) * 8;
    const int a_c = (lane >> 4) * 4;
    const uint32_t q_lm = sbase + (((wr0 + a_r) * QH) + a_c) * 4;
    const int k_r = (lane & 7) + (lane >> 4) * 8;
    const int k_c = ((lane >> 3) & 1) * 4;
    const int m4  = lane >> 3;
    const int v_r = (m4 & 1) * 8 + (lane & 7);
    const int v_c = (m4 >> 1) * 4;
    const uint32_t v_lm = (v_r * VH + v_c) * 4;

    #pragma unroll
    for (int t = 0; t < 8; ++t) {
        int i = tid + t * 128;
        int r = i >> 3, c4 = (i & 7) * 4;
        cp16(sbase + (r * QH + c4) * 4, &Qh[pbase + (size_t)(q0 + r) * 32 + c4]);
    }
    #pragma unroll
    for (int t = 0; t < 4; ++t) {
        int i = tid + t * 128;
        int r = i >> 3, c4 = (i & 7) * 4;
        cp16(sbase + (OFF_KP0 + r * KP + c4) * 4, &Kh[pbase + (size_t)r * 32 + c4]);
        cp16(sbase + (OFF_V0 + r * VH + c4) * 4, &Vh[pbase + (size_t)r * 32 + c4]);
    }
    if (tid < 16) cp16(sbase + (OFF_M0 + tid * 4) * 4, &mask[b * S_ + tid * 4]);
    CP_COMMIT();

    float mrun[4] = {-1e30f, -1e30f, -1e30f, -1e30f};
    float lrun[4] = {0.f, 0.f, 0.f, 0.f};
    float o[2][8][4];
    #pragma unroll
    for (int at = 0; at < 2; ++at)
        #pragma unroll
        for (int nt = 0; nt < 8; ++nt)
            #pragma unroll
            for (int r = 0; r < 4; ++r) o[at][nt][r] = 0.f;

    for (int it = 0; it < 32; ++it) {
        const int bu = it & 1;
        const uint32_t kpo = bu ? OFF_KP1 : OFF_KP0;
        const uint32_t vpo = bu ? OFF_V1  : OFF_V0;
        const float* msk = (const float*)(sm + (bu ? OFF_M1 : OFF_M0));
        const uint32_t k_lm = sbase + kpo * 4 + (k_r * KP + k_c) * 4;
        const uint32_t v_lmb = sbase + vpo * 4 + v_lm;

        CP_WAIT0();
        __syncthreads();

        if (it + 1 < 32) {
            const int kn = (it + 1) * 64;
            const uint32_t kdo = bu ? OFF_KP0 : OFF_KP1;
            const uint32_t vdo = bu ? OFF_V0  : OFF_V1;
            #pragma unroll
            for (int t = 0; t < 4; ++t) {
                int i = tid + t * 128;
                int r = i >> 3, c4 = (i & 7) * 4;
                cp16(sbase + (kdo + r * KP + c4) * 4,
                     &Kh[pbase + (size_t)(kn + r) * 32 + c4]);
                cp16(sbase + (vdo + r * VH + c4) * 4,
                     &Vh[pbase + (size_t)(kn + r) * 32 + c4]);
            }
            if (tid < 16)
                cp16(sbase + ((bu ? OFF_M0 : OFF_M1) + tid * 4) * 4,
                     &mask[b * S_ + kn + tid * 4]);
            CP_COMMIT();
        }

        // ---- S = Q @ K^T ----
        float s[2][8][4];
        #pragma unroll
        for (int at = 0; at < 2; ++at)
            #pragma unroll
            for (int nt = 0; nt < 8; ++nt)
                #pragma unroll
                for (int r = 0; r < 4; ++r) s[at][nt][r] = 0.f;

        #pragma unroll
        for (int ks = 0; ks < 4; ++ks) {
            uint32_t bfr[8][2];
            #pragma unroll
            for (int ntp = 0; ntp < 4; ++ntp)
                LDM_X4(bfr[2 * ntp][0], bfr[2 * ntp][1],
                       bfr[2 * ntp + 1][0], bfr[2 * ntp + 1][1],
                       k_lm + (ntp * 16 * KP + ks * 8) * 4);
            #pragma unroll
            for (int at = 0; at < 2; ++at) {
                uint32_t a[4];
                LDM_X4(a[0], a[1], a[2], a[3],
                       q_lm + (at * 16 * QH + ks * 8) * 4);
                #pragma unroll
                for (int nt = 0; nt < 8; ++nt)
                    MMA_F16(s[at][nt], a, bfr[nt]);
            }
        }

        // ---- mask + online softmax (base-2); P -> f16x2 ----
        uint32_t pb[2][8][2];
        #pragma unroll
        for (int at = 0; at < 2; ++at) {
            float rmax0 = -1e30f, rmax1 = -1e30f;
            #pragma unroll
            for (int nt = 0; nt < 8; ++nt) {
                int c0 = nt * 8 + 2 * thr;
                float mk0 = msk[c0], mk1 = msk[c0 + 1];
                s[at][nt][0] = fmaf(mk0, LOG2E, s[at][nt][0]);
                s[at][nt][1] = fmaf(mk1, LOG2E, s[at][nt][1]);
                s[at][nt][2] = fmaf(mk0, LOG2E, s[at][nt][2]);
                s[at][nt][3] = fmaf(mk1, LOG2E, s[at][nt][3]);
                rmax0 = fmaxf(rmax0, fmaxf(s[at][nt][0], s[at][nt][1]));
                rmax1 = fmaxf(rmax1, fmaxf(s[at][nt][2], s[at][nt][3]));
            }
            rmax0 = fmaxf(rmax0, __shfl_xor_sync(0xffffffffu, rmax0, 1));
            rmax0 = fmaxf(rmax0, __shfl_xor_sync(0xffffffffu, rmax0, 2));
            rmax1 = fmaxf(rmax1, __shfl_xor_sync(0xffffffffu, rmax1, 1));
            rmax1 = fmaxf(rmax1, __shfl_xor_sync(0xffffffffu, rmax1, 2));

            const int g0 = at * 2, g1 = at * 2 + 1;
            const float mnew0 = fmaxf(mrun[g0], rmax0);
            const float mnew1 = fmaxf(mrun[g1], rmax1);
            float sum0 = 0.f, sum1 = 0.f;
            #pragma unroll
            for (int nt = 0; nt < 8; ++nt) {
                s[at][nt][0] = ex2(s[at][nt][0] - mnew0);
                s[at][nt][1] = ex2(s[at][nt][1] - mnew0);
                s[at][nt][2] = ex2(s[at][nt][2] - mnew1);
                s[at][nt][3] = ex2(s[at][nt][3] - mnew1);
                sum0 += s[at][nt][0] + s[at][nt][1];
                sum1 += s[at][nt][2] + s[at][nt][3];
                pb[at][nt][0] = pack_f16x2(s[at][nt][0], s[at][nt][1]);
                pb[at][nt][1] = pack_f16x2(s[at][nt][2], s[at][nt][3]);
            }
            sum0 += __shfl_xor_sync(0xffffffffu, sum0, 1);
            sum0 += __shfl_xor_sync(0xffffffffu, sum0, 2);
            sum1 += __shfl_xor_sync(0xffffffffu, sum1, 1);
            sum1 += __shfl_xor_sync(0xffffffffu, sum1, 2);

            const float cf0 = ex2(mrun[g0] - mnew0);
            const float cf1 = ex2(mrun[g1] - mnew1);
            mrun[g0] = mnew0;  lrun[g0] = lrun[g0] * cf0 + sum0;
            mrun[g1] = mnew1;  lrun[g1] = lrun[g1] * cf1 + sum1;

            #pragma unroll
            for (int nt = 0; nt < 8; ++nt) {
                o[at][nt][0] *= cf0;  o[at][nt][1] *= cf0;
                o[at][nt][2] *= cf1;  o[at][nt][3] *= cf1;
            }
        }

        // ---- O += P @ V (ldmatrix.trans B-frags) ----
        #pragma unroll
        for (int sstep = 0; sstep < 4; ++sstep) {
            uint32_t bfr[8][2];
            #pragma unroll
            for (int ntp = 0; ntp < 4; ++ntp)
                LDM_X4T(bfr[2 * ntp][0], bfr[2 * ntp][1],
                        bfr[2 * ntp + 1][0], bfr[2 * ntp + 1][1],
                        v_lmb + (sstep * 16 * VH + ntp * 8) * 4);
            #pragma unroll
            for (int at = 0; at < 2; ++at) {
                uint32_t a[4] = {pb[at][2 * sstep][0], pb[at][2 * sstep][1],
                                 pb[at][2 * sstep + 1][0], pb[at][2 * sstep + 1][1]};
                #pragma unroll
                for (int nt = 0; nt < 8; ++nt)
                    MMA_F16(o[at][nt], a, bfr[nt]);
            }
        }
    }

    // Output
    #pragma unroll
    for (int at = 0; at < 2; ++at) {
        #pragma unroll
        for (int half = 0; half < 2; ++half) {
            const int g = at * 2 + half;
            const float inv = 1.f / lrun[g];
            const int q = q0 + wr0 + at * 16 + grp + half * 8;
            #pragma unroll
            for (int nt = 0; nt < 8; ++nt) {
                int d = nt * 8 + 2 * thr;
                float2 v = {o[at][nt][half * 2 + 0] * inv,
                            o[at][nt][half * 2 + 1] * inv};
                *reinterpret_cast<float2*>(
                    &out[((size_t)(b * S_ + q)) * HID + h * D_ + d]) = v;
            }
        }
    }
}

// ---------------------------------------------------------------------------
// Launch
// ---------------------------------------------------------------------------
extern "C" void kernel_launch(void* const* d_in, const int* in_sizes, int n_in,
                              void* d_out, int out_size)
{
    const float* X    = (const float*)d_in[0];
    const float* mask = (const float*)d_in[1];
    const float* Wq   = (const float*)d_in[2];
    const float* bq   = (const float*)d_in[3];
    const float* Wk   = (const float*)d_in[4];
    const float* bk   = (const float*)d_in[5];
    const float* Wv   = (const float*)d_in[6];
    const float* bv   = (const float*)d_in[7];
    float* out = (float*)d_out;

    uint32_t *dXh, *dWhq, *dWhk, *dWhv, *dQ, *dK, *dV;
    cudaGetSymbolAddress((void**)&dXh,  g_Xh);
    cudaGetSymbolAddress((void**)&dWhq, g_Whq);
    cudaGetSymbolAddress((void**)&dWhk, g_Whk);
    cudaGetSymbolAddress((void**)&dWhv, g_Whv);
    cudaGetSymbolAddress((void**)&dQ,   g_Qh);
    cudaGetSymbolAddress((void**)&dK,   g_Kh);
    cudaGetSymbolAddress((void**)&dV,   g_Vh);

    cudaFuncSetAttribute(qkv_gemm3, cudaFuncAttributeMaxDynamicSharedMemorySize, GEMM_SMEM);
    const int attn_smem = ATTN_WORDS * 4;
    cudaFuncSetAttribute(attn_f16, cudaFuncAttributeMaxDynamicSharedMemorySize, attn_smem);

    dim3 pgrid(512, 4);
    pack_inputs<<<pgrid, 256>>>(X, Wq, Wk, Wv, dXh, dWhq, dWhk, dWhv);

    dim3 ggrid(HID / 128, M_ / 128, 3);   // (8, 64, 3)
    qkv_gemm3<<<ggrid, 256, GEMM_SMEM>>>(dXh, dWhq, dWhk, dWhv, bq, bk, bv, dQ, dK, dV);

    dim3 agrid(S_ / 128, H_, B_);         // (16, 16, 4)
    attn_f16<<<agrid, 128, attn_smem>>>(dQ, dK, dV, mask, out);
}